// round 12
// baseline (speedup 1.0000x reference)
#include <cuda_runtime.h>
#include <cuda_bf16.h>
#include <cuda_fp16.h>
#include <math.h>
#include <stdint.h>

#define Bq    4
#define Hh    12
#define Cc    1024
#define Dd    768
#define Ee    30
#define Mm    8
#define Pp    600
#define NL    97
#define RELSn 96
#define EMBn  768
#define NTOT  2400   // B*P
#define NPAD  2560   // pad rows stay zero
#define NSPLIT 12    // k blocks

// ---------------- scratch (static device globals; no allocation) -------------
__device__ float g_ent_emb[Bq*Ee*Dd];          // [B,E,D]
__device__ float g_ent_att[Bq*Ee*Hh*Cc];       // [B,E,H,C]
__device__ float g_hz[NPAD*EMBn];              // rows >=2400 stay zero
__device__ float g_tz[NPAD*EMBn];
__device__ uint32_t g_wtf[768*3072];           // bil W fp16 hi: [blob][64 j][48 lpair]
__device__ uint32_t g_wtl[768*3072];           // bil W fp16 lo (residual)
__device__ float    g_w96[768*64];             // bil W col 96: [blob][j]
__device__ uint32_t g_ht_hi[Bq*640*512];       // ht_att bf16 pairs [b][640][512]
__device__ uint32_t g_ht_lo[Bq*640*512];
__device__ uint32_t g_seq_hi[Bq*Cc*384];       // seq bf16 pairs [b][1024][384]
__device__ uint32_t g_seq_lo[Bq*Cc*384];
__device__ uint32_t g_rs_hi[2432*384];         // rs bf16 pairs (pad rows zero)
__device__ uint32_t g_rs_lo[2432*384];
__device__ uint32_t g_wb_hi[768*768];          // [W_bot_head | W_bot_tail] pairs
__device__ uint32_t g_wb_lo[768*768];
__device__ float g_U[2*Bq*Ee*EMBn];            // ent_emb @ W_top (head, tail)
__device__ float g_part[NSPLIT*NPAD*128];      // split partial logits
__device__ float g_riskc[RELSn];
__device__ unsigned int g_rdone = 0;

// =================== helpers ===================================================
__device__ __forceinline__ uint32_t smem_u32(const void* p) {
    uint32_t a;
    asm("{ .reg .u64 t; cvta.to.shared.u64 t, %1; cvt.u32.u64 %0, t; }" : "=r"(a) : "l"(p));
    return a;
}
__device__ __forceinline__ void pack2(float p0, float p1, uint32_t& hi, uint32_t& lo) {
    uint32_t h;
    asm("cvt.rn.bf16x2.f32 %0, %1, %2;" : "=r"(h) : "f"(p1), "f"(p0));
    float h0 = __uint_as_float(h << 16);
    float h1 = __uint_as_float(h & 0xFFFF0000u);
    float l0 = p0 - h0, l1 = p1 - h1;
    uint32_t l;
    asm("cvt.rn.bf16x2.f32 %0, %1, %2;" : "=r"(l) : "f"(l1), "f"(l0));
    hi = h; lo = l;
}
__device__ __forceinline__ void pack2h(float p0, float p1, uint32_t& hi, uint32_t& lo) {
    __half2 h = __floats2half2_rn(p0, p1);
    float2 hf = __half22float2(h);
    __half2 l = __floats2half2_rn(p0 - hf.x, p1 - hf.y);
    hi = *(uint32_t*)&h;
    lo = *(uint32_t*)&l;
}
__device__ __forceinline__ void ldm_x4(uint32_t* r, uint32_t addr) {
    asm volatile("ldmatrix.sync.aligned.m8n8.x4.shared.b16 {%0,%1,%2,%3}, [%4];"
        : "=r"(r[0]), "=r"(r[1]), "=r"(r[2]), "=r"(r[3]) : "r"(addr));
}
__device__ __forceinline__ void ldm_x4_t(uint32_t* r, uint32_t addr) {
    asm volatile("ldmatrix.sync.aligned.m8n8.x4.trans.shared.b16 {%0,%1,%2,%3}, [%4];"
        : "=r"(r[0]), "=r"(r[1]), "=r"(r[2]), "=r"(r[3]) : "r"(addr));
}
__device__ __forceinline__ void mma_bf16(float* d, const uint32_t* a, const uint32_t* b) {
    asm volatile(
        "mma.sync.aligned.m16n8k16.row.col.f32.bf16.bf16.f32 "
        "{%0,%1,%2,%3}, {%4,%5,%6,%7}, {%8,%9}, {%0,%1,%2,%3};"
        : "+f"(d[0]), "+f"(d[1]), "+f"(d[2]), "+f"(d[3])
        : "r"(a[0]), "r"(a[1]), "r"(a[2]), "r"(a[3]), "r"(b[0]), "r"(b[1]));
}
__device__ __forceinline__ void mma_f16(float* d, const uint32_t* a, const uint32_t* b) {
    asm volatile(
        "mma.sync.aligned.m16n8k16.row.col.f32.f16.f16.f32 "
        "{%0,%1,%2,%3}, {%4,%5,%6,%7}, {%8,%9}, {%0,%1,%2,%3};"
        : "+f"(d[0]), "+f"(d[1]), "+f"(d[2]), "+f"(d[3])
        : "r"(a[0]), "r"(a[1]), "r"(a[2]), "r"(a[3]), "r"(b[0]), "r"(b[1]));
}
#define CPASYNC(dst, src) asm volatile("cp.async.cg.shared.global [%0], [%1], 16;" :: "r"(dst), "l"(src))
#define CPCOMMIT()        asm volatile("cp.async.commit_group;")
#define CPWAIT(n)         asm volatile("cp.async.wait_group %0;" :: "n"(n) : "memory")

// ---------------- K_PREP: fused ent_att | wsplit | ent_emb | wbsplit | seqsplit -
__global__ __launch_bounds__(256) void k_prep(
    const float* __restrict__ seq, const float* __restrict__ att,
    const int* __restrict__ midx, const float* __restrict__ mmask,
    const float* __restrict__ bilW,
    const float* __restrict__ hW, const float* __restrict__ tW)
{
    int bid = blockIdx.x;
    int tid = threadIdx.x;
    __shared__ int   s_idx[Mm];
    __shared__ float s_w[Mm];

    if (bid < 1440) {
        int g  = bid;
        int h  = g % Hh;
        int be = g / Hh;
        int b  = be / Ee;
        if (tid < Mm) {
            s_idx[tid] = midx[be*Mm + tid] + 1;
            s_w[tid]   = mmask[be*Mm + tid];
        }
        __syncthreads();
        float cnt = 0.f;
#pragma unroll
        for (int m = 0; m < Mm; m++) cnt += s_w[m];
        float inv = 1.f / cnt;
        const float* base = att + ((size_t)b*Hh + h)*Cc*Cc;
        for (int c = tid; c < Cc; c += 256) {
            float s = 0.f;
#pragma unroll
            for (int m = 0; m < Mm; m++)
                s += s_w[m] * base[(size_t)s_idx[m]*Cc + c];
            g_ent_att[(size_t)g*Cc + c] = s * inv;
        }
    } else if (bid < 2208) {
        int blob = bid - 1440;
        int j = tid >> 2, lq = (tid & 3) * 24;
        size_t row = ((size_t)blob*64 + j) * NL;
        uint32_t* oh = g_wtf + ((size_t)blob*64 + j)*48 + (lq >> 1);
        uint32_t* ol = g_wtl + ((size_t)blob*64 + j)*48 + (lq >> 1);
#pragma unroll
        for (int q = 0; q < 12; q++) {
            int l0 = lq + q*2;
            float v0 = bilW[row + l0];
            float v1 = bilW[row + l0 + 1];
            uint32_t h, l;
            pack2h(v0, v1, h, l);
            oh[q] = h; ol[q] = l;
        }
        if ((tid & 3) == 0) g_w96[(size_t)blob*64 + j] = bilW[row + 96];
    } else if (bid < 2328) {
        int be = bid - 2208;
        int b  = be / Ee;
        if (tid < Mm) {
            s_idx[tid] = midx[be*Mm + tid] + 1;
            s_w[tid]   = mmask[be*Mm + tid];
        }
        __syncthreads();
        for (int d = tid; d < Dd; d += 256) {
            float xv[Mm];
            float mx = -1e30f;
#pragma unroll
            for (int m = 0; m < Mm; m++) {
                float x = seq[((size_t)b*Cc + s_idx[m])*Dd + d];
                xv[m] = x;
                if (s_w[m] > 0.f) mx = fmaxf(mx, x);
            }
            float s = 0.f;
#pragma unroll
            for (int m = 0; m < Mm; m++)
                if (s_w[m] > 0.f) s += s_w[m] * __expf(xv[m] - mx);
            g_ent_emb[(size_t)be*Dd + d] = __logf(s) + mx;
        }
    } else if (bid < 2904) {
        int i0 = (bid - 2328)*1024 + tid*4;
#pragma unroll
        for (int q = 0; q < 4; q++) {
            int i = i0 + q;
            int kk = i / 768, c = i % 768;
            int c2 = c*2;
            const float* W = (c2 < 768) ? hW : tW;
            int col = (c2 < 768) ? c2 : (c2 - 768);
            size_t ro = (size_t)(768 + kk) * EMBn;
            uint32_t h, l;
            pack2(W[ro + col], W[ro + col + 1], h, l);
            g_wb_hi[i] = h; g_wb_lo[i] = l;
        }
    } else {
        int i0 = (bid - 2904)*1024 + tid*4;
#pragma unroll
        for (int q = 0; q < 4; q++) {
            int i = i0 + q;
            uint32_t h, l;
            pack2(seq[(size_t)i*2], seq[(size_t)i*2+1], h, l);
            g_seq_hi[i] = h; g_seq_lo[i] = l;
        }
    }
}

// ---------------- K_HT: ht_att -> bf16 hi/lo split ------------------------------
__global__ void k_ht(const int* __restrict__ hts) {
    int n = blockIdx.x;
    int b = n / Pp, p = n % Pp;
    int hi = hts[n*2 + 0], ti = hts[n*2 + 1];
    size_t hb = (size_t)(b*Ee + hi) * Hh * Cc;
    size_t tb = (size_t)(b*Ee + ti) * Hh * Cc;
    __shared__ float vals[Cc];
    __shared__ float red[256];
    float loc = 0.f;
    for (int c = threadIdx.x; c < Cc; c += 256) {
        float s = 0.f;
#pragma unroll
        for (int h = 0; h < Hh; h++)
            s += g_ent_att[hb + (size_t)h*Cc + c] * g_ent_att[tb + (size_t)h*Cc + c];
        s *= (1.f / Hh);
        vals[c] = s;
        loc += s;
    }
    red[threadIdx.x] = loc;
    __syncthreads();
    for (int st = 128; st > 0; st >>= 1) {
        if (threadIdx.x < st) red[threadIdx.x] += red[threadIdx.x + st];
        __syncthreads();
    }
    float invt = 1.f / (red[0] + 1e-5f);
    uint32_t* oh = g_ht_hi + ((size_t)b*640 + p)*512;
    uint32_t* ol = g_ht_lo + ((size_t)b*640 + p)*512;
    for (int c2 = threadIdx.x; c2 < 512; c2 += 256) {
        float v0 = vals[c2*2]   * invt;
        float v1 = vals[c2*2+1] * invt;
        uint32_t h, l;
        pack2(v0, v1, h, l);
        oh[c2] = h; ol[c2] = l;
    }
}

// ---------------- pipelined bf16x3 GEMM (128x128 tile, k-chunk 32, occ2) -------
// smem: A[stage][hi/lo] 2x20480 | B[stage][hi/lo] 2x17408 -> 75776
#define PA_STG 20480
#define PB_OFF 40960
#define PB_STG 17408
#define GEMM_SM 75776

__device__ __forceinline__ void gemm_main(float acc[4][4][4],
    const uint32_t* __restrict__ Ah, const uint32_t* __restrict__ Al,
    const uint32_t* __restrict__ Bh, const uint32_t* __restrict__ Bl,
    int K, int N, int m0, int n0)
{
    extern __shared__ char sm[];
    uint32_t smb = smem_u32(sm);
    int tid = threadIdx.x, lane = tid & 31, wid = tid >> 5;
    int lda32 = K >> 1, ldb32 = N >> 1;
    int nch = K >> 5;
    int wn = wid >> 2, wl = wid & 3, lq = lane & 15, lh = lane >> 4;
    uint32_t a_frag = (wn*64 + lq)*80 + lh*16;
    uint32_t b_frag = lq*272 + (wl*64 + lh*16);
    // staging indices
    int ar = tid >> 2, ac4 = tid & 3;            // A: 128 rows x 4 u4 (x2 reps of 512)
    int br = tid >> 4, bc4 = tid & 15;           // B: 32 rows x 16 u4 (x2 reps of 512)

    // ---- prefetch chunk 0 into stage 0
    {
        size_t ga0 = (size_t)(m0 + ar)*lda32 + ac4*4;
        size_t ga1 = (size_t)(m0 + ar + 64)*lda32 + ac4*4;
        CPASYNC(smb + ar*80 + ac4*16, (const uint4*)&Ah[ga0]);
        CPASYNC(smb + (ar + 64)*80 + ac4*16, (const uint4*)&Ah[ga1]);
        CPASYNC(smb + 10240 + ar*80 + ac4*16, (const uint4*)&Al[ga0]);
        CPASYNC(smb + 10240 + (ar + 64)*80 + ac4*16, (const uint4*)&Al[ga1]);
        size_t gb0 = (size_t)br*ldb32 + (n0 >> 1) + bc4*4;
        size_t gb1 = (size_t)(br + 16)*ldb32 + (n0 >> 1) + bc4*4;
        CPASYNC(smb + PB_OFF + br*272 + bc4*16, (const uint4*)&Bh[gb0]);
        CPASYNC(smb + PB_OFF + (br + 16)*272 + bc4*16, (const uint4*)&Bh[gb1]);
        CPASYNC(smb + PB_OFF + 8704 + br*272 + bc4*16, (const uint4*)&Bl[gb0]);
        CPASYNC(smb + PB_OFF + 8704 + (br + 16)*272 + bc4*16, (const uint4*)&Bl[gb1]);
        CPCOMMIT();
    }

    for (int c = 0; c < nch; c++) {
        int st = c & 1;
        if (c + 1 < nch) {
            int ns = (c + 1) & 1;
            int kc32 = (c + 1) * 16;   // u32 offset of next chunk
            uint32_t abase = smb + ns*PA_STG;
            uint32_t bbase = smb + PB_OFF + ns*PB_STG;
            size_t ga0 = (size_t)(m0 + ar)*lda32 + kc32 + ac4*4;
            size_t ga1 = (size_t)(m0 + ar + 64)*lda32 + kc32 + ac4*4;
            CPASYNC(abase + ar*80 + ac4*16, (const uint4*)&Ah[ga0]);
            CPASYNC(abase + (ar + 64)*80 + ac4*16, (const uint4*)&Ah[ga1]);
            CPASYNC(abase + 10240 + ar*80 + ac4*16, (const uint4*)&Al[ga0]);
            CPASYNC(abase + 10240 + (ar + 64)*80 + ac4*16, (const uint4*)&Al[ga1]);
            int kr = (c + 1) * 32;
            size_t gb0 = (size_t)(kr + br)*ldb32 + (n0 >> 1) + bc4*4;
            size_t gb1 = (size_t)(kr + br + 16)*ldb32 + (n0 >> 1) + bc4*4;
            CPASYNC(bbase + br*272 + bc4*16, (const uint4*)&Bh[gb0]);
            CPASYNC(bbase + (br + 16)*272 + bc4*16, (const uint4*)&Bh[gb1]);
            CPASYNC(bbase + 8704 + br*272 + bc4*16, (const uint4*)&Bl[gb0]);
            CPASYNC(bbase + 8704 + (br + 16)*272 + bc4*16, (const uint4*)&Bl[gb1]);
            CPCOMMIT();
            CPWAIT(1);
        } else {
            CPWAIT(0);
        }
        __syncthreads();
        uint32_t a_base  = smb + st*PA_STG + a_frag;
        uint32_t al_base = a_base + 10240;
        uint32_t b_base  = smb + PB_OFF + st*PB_STG + b_frag;
        uint32_t bl_base = b_base + 8704;
#pragma unroll
        for (int kt = 0; kt < 2; kt++) {
            uint32_t a_hi[4][4], a_lo[4][4];
#pragma unroll
            for (int mt = 0; mt < 4; mt++) {
                ldm_x4(a_hi[mt], a_base  + mt*1280 + kt*32);
                ldm_x4(a_lo[mt], al_base + mt*1280 + kt*32);
            }
#pragma unroll
            for (int lt = 0; lt < 2; lt++) {
                uint32_t b_hi[4], b_lo[4];
                ldm_x4_t(b_hi, b_base  + kt*4352 + lt*32);
                ldm_x4_t(b_lo, bl_base + kt*4352 + lt*32);
#pragma unroll
                for (int mt = 0; mt < 4; mt++) {
#pragma unroll
                    for (int f = 0; f < 2; f++) {
                        float* d = acc[mt][lt*2 + f];
                        mma_bf16(d, a_hi[mt], &b_hi[f*2]);
                        mma_bf16(d, a_lo[mt], &b_hi[f*2]);
                        mma_bf16(d, a_hi[mt], &b_lo[f*2]);
                    }
                }
            }
        }
        __syncthreads();
    }
}

// ---------------- K_RS_ENTU: fused rs GEMM (120 blocks) + entU (48 blocks) -----
__global__ __launch_bounds__(256, 2) void k_rs_entU(const float* __restrict__ hW,
                                                    const float* __restrict__ tW) {
    extern __shared__ char sm[];
    int bid = blockIdx.x;
    int tid = threadIdx.x;
    if (bid < 120) {
        int b = bid / 30;
        int rem = bid % 30;
        int m0 = (rem % 5) * 128, n0 = (rem / 5) * 128;
        float acc[4][4][4] = {};
        gemm_main(acc,
                  g_ht_hi + (size_t)b*640*512, g_ht_lo + (size_t)b*640*512,
                  g_seq_hi + (size_t)b*Cc*384, g_seq_lo + (size_t)b*Cc*384,
                  Cc, Dd, m0, n0);
        int lane = tid & 31, wid = tid >> 5;
        int wn = wid >> 2, wl = wid & 3;
        int rbase = m0 + wn*64 + (lane >> 2);
        int cbase = n0 + wl*32 + (lane & 3)*2;
#pragma unroll
        for (int mt = 0; mt < 4; mt++) {
#pragma unroll
            for (int lf = 0; lf < 4; lf++) {
                int r = rbase + mt*16;
                int cp = (cbase + lf*8) >> 1;
                float* d = acc[mt][lf];
                if (r < Pp) {
                    uint32_t h, l;
                    pack2(d[0], d[1], h, l);
                    g_rs_hi[((size_t)(b*Pp + r))*384 + cp] = h;
                    g_rs_lo[((size_t)(b*Pp + r))*384 + cp] = l;
                }
                if (r + 8 < Pp) {
                    uint32_t h, l;
                    pack2(d[2], d[3], h, l);
                    g_rs_hi[((size_t)(b*Pp + r + 8))*384 + cp] = h;
                    g_rs_lo[((size_t)(b*Pp + r + 8))*384 + cp] = l;
                }
            }
        }
    } else {
        // ---- entU: ent_emb @ W_top (SIMT)
        int idx = bid - 120;
        int mb = (idx & 1) * 64;
        int nb = ((idx >> 1) % 12) * 64;
        int s  = idx / 24;
        const float* W = s ? tW : hW;
        float* As = (float*)sm;
        float* Bs = (float*)(sm + 4096);
        int tm = tid >> 4, tn = tid & 15;
        int lm = tid & 63, lk4 = (tid >> 6) << 2;
        float acc[4][4] = {};
        for (int kc = 0; kc < Dd; kc += 16) {
            float4 av = make_float4(0.f,0.f,0.f,0.f);
            int m = mb + lm;
            if (m < Bq*Ee) av = *(const float4*)&g_ent_emb[(size_t)m*Dd + kc + lk4];
            As[(lk4+0)*64+lm] = av.x; As[(lk4+1)*64+lm] = av.y;
            As[(lk4+2)*64+lm] = av.z; As[(lk4+3)*64+lm] = av.w;
#pragma unroll
            for (int r = 0; r < 4; r++) {
                int kk = lk4 + r;
                Bs[kk*64+lm] = W[(size_t)(kc+kk)*EMBn + nb + lm];
            }
            __syncthreads();
#pragma unroll
            for (int kk = 0; kk < 16; kk++) {
                float4 a4 = *(const float4*)&As[kk*64 + tm*4];
                float4 b4 = *(const float4*)&Bs[kk*64 + tn*4];
                acc[0][0] += a4.x*b4.x; acc[0][1] += a4.x*b4.y; acc[0][2] += a4.x*b4.z; acc[0][3] += a4.x*b4.w;
                acc[1][0] += a4.y*b4.x; acc[1][1] += a4.y*b4.y; acc[1][2] += a4.y*b4.z; acc[1][3] += a4.y*b4.w;
                acc[2][0] += a4.z*b4.x; acc[2][1] += a4.z*b4.y; acc[2][2] += a4.z*b4.z; acc[2][3] += a4.z*b4.w;
                acc[3][0] += a4.w*b4.x; acc[3][1] += a4.w*b4.y; acc[3][2] += a4.w*b4.z; acc[3][3] += a4.w*b4.w;
            }
            __syncthreads();
        }
#pragma unroll
        for (int a = 0; a < 4; a++) {
            int m = mb + tm*4 + a;
            if (m < Bq*Ee)
                *(float4*)&g_U[((size_t)s*Bq*Ee + m)*EMBn + nb + tn*4] =
                    make_float4(acc[a][0], acc[a][1], acc[a][2], acc[a][3]);
        }
    }
}

// ---------------- K_RW: rs @ [Wbh|Wbt]; fused U-gather + bias + tanh ------------
__global__ __launch_bounds__(256, 2) void k_rw_mma(const int* __restrict__ hts,
                                                   const float* __restrict__ hb,
                                                   const float* __restrict__ tb) {
    int m0 = blockIdx.x * 128, n0 = blockIdx.y * 128;
    float acc[4][4][4] = {};
    gemm_main(acc, g_rs_hi, g_rs_lo, g_wb_hi, g_wb_lo, Dd, 1536, m0, n0);
    int tid = threadIdx.x, lane = tid & 31, wid = tid >> 5;
    int wn = wid >> 2, wl = wid & 3;
    int rbase = m0 + wn*64 + (lane >> 2);
    int cbase = n0 + wl*32 + (lane & 3)*2;
#pragma unroll
    for (int mt = 0; mt < 4; mt++) {
#pragma unroll
        for (int rr = 0; rr < 2; rr++) {
            int r = rbase + mt*16 + rr*8;
            if (r >= NTOT) continue;
            int b = r / Pp;
            int e0 = hts[r*2 + 0], e1 = hts[r*2 + 1];
#pragma unroll
            for (int lf = 0; lf < 4; lf++) {
                int c = cbase + lf*8;
                int s = (c >= 768);
                int cc = c - (s ? 768 : 0);
                int e = s ? e1 : e0;
                const float* Ur = g_U + ((size_t)(s*Bq*Ee + b*Ee + e))*EMBn + cc;
                const float* bi = (s ? tb : hb) + cc;
                float* dst = (s ? g_tz : g_hz) + (size_t)r*EMBn + cc;
                float* d = acc[mt][lf];
                float2 o;
                o.x = tanhf(d[rr*2 + 0] + Ur[0] + bi[0]);
                o.y = tanhf(d[rr*2 + 1] + Ur[1] + bi[1]);
                *(float2*)dst = o;
            }
        }
    }
}

// ---------------- K_BILIN_C96: fp16x3 bilinear (240 @128-row, occ2) + c96 (228) -
#define SB_AH 0          // A hi: 128 x 144B
#define SB_AL 18432      // A lo
#define SB_B0 36864      // B stages: 2 x (hi 13312 + lo 13312)
#define SB_BUF 26624
#define SB_TOT 90112

__global__ __launch_bounds__(256, 2) void k_bilin_c96() {
    extern __shared__ char sm[];
    uint32_t smb = smem_u32(sm);
    int bid = blockIdx.x;
    int tid = threadIdx.x, lane = tid & 31, wid = tid >> 5;

    if (bid >= 240) {
        // ---- c96: exact fp32 column 96 (128-row tiles)
        int idx = bid - 240;
        int n0 = (idx % 19) * 128, k = idx / 19;
        float* Ws  = (float*)sm;          // [64][64]
        float* hzs = Ws + 4096;           // [128][65]
        float* tzs = hzs + 128*65;        // [128][65]
        for (int e = tid; e < 4096; e += 256)
            Ws[e] = g_w96[(size_t)k*4096 + e];
        for (int e = tid; e < 128*64; e += 256) {
            int r = e >> 6, c = e & 63;
            int n = n0 + r;
            float hv = 0.f, tv = 0.f;
            if (n < NTOT) {
                hv = g_hz[(size_t)n*EMBn + k*64 + c];
                tv = g_tz[(size_t)n*EMBn + k*64 + c];
            }
            hzs[r*65 + c] = hv;
            tzs[r*65 + c] = tv;
        }
        __syncthreads();
        if (tid < 128) {
            float tzr[64];
#pragma unroll
            for (int j = 0; j < 64; j++) tzr[j] = tzs[tid*65 + j];
            float acc = 0.f;
            for (int i = 0; i < 64; i++) {
                const float4* wr = (const float4*)&Ws[i*64];
                float s = 0.f;
#pragma unroll
                for (int j4 = 0; j4 < 16; j4++) {
                    float4 w = wr[j4];
                    s += w.x*tzr[j4*4] + w.y*tzr[j4*4+1] + w.z*tzr[j4*4+2] + w.w*tzr[j4*4+3];
                }
                acc += hzs[tid*65 + i] * s;
            }
            int n = n0 + tid;
            if (n < NTOT) g_part[((size_t)k*NPAD + n)*128 + 96] = acc;
        }
        return;
    }

    // ---- bilinear: 128-row tile, wn4 x wl2
    int n0 = (bid % 20) * 128, k = bid / 20;
    int anl = tid >> 1, ajh = tid & 1;

    float tz[32];
    {
        const float* tzp = g_tz + (size_t)(n0 + anl)*EMBn + k*64 + ajh*32;
#pragma unroll
        for (int j = 0; j < 32; j++) tz[j] = tzp[j];
    }
    const float* hzp = g_hz + (size_t)(n0 + anl)*EMBn + k*64;

    int wn = wid >> 1, wl = wid & 1;
    int lq = lane & 15, lh = lane >> 4;
    uint32_t a_base  = smb + SB_AH + (wn*32 + lq)*144 + lh*16;
    uint32_t al_base = a_base + (SB_AL - SB_AH);
    uint32_t b_off   = lq*208 + wl*96 + lh*16;

    {
        const uint4* srch = ((const uint4*)g_wtf) + (size_t)(k*64)*768;
        const uint4* srcl = ((const uint4*)g_wtl) + (size_t)(k*64)*768;
#pragma unroll
        for (int rep = 0; rep < 3; rep++) {
            int idx = tid + rep*256;
            int j = idx / 12, c = idx % 12;
            CPASYNC(smb + SB_B0 + j*208 + c*16, srch + idx);
            CPASYNC(smb + SB_B0 + 13312 + j*208 + c*16, srcl + idx);
        }
        CPCOMMIT();
    }

    float acc[2][6][4] = {};

    for (int i = 0; i < 64; i++) {
        if (i < 63) {
            size_t blob = (size_t)(k*64 + i + 1) * 768;
            const uint4* srch = ((const uint4*)g_wtf) + blob;
            const uint4* srcl = ((const uint4*)g_wtl) + blob;
            uint32_t dst = smb + SB_B0 + ((i + 1) & 1) * SB_BUF;
#pragma unroll
            for (int rep = 0; rep < 3; rep++) {
                int idx = tid + rep*256;
                int j = idx / 12, c = idx % 12;
                CPASYNC(dst + j*208 + c*16, srch + idx);
                CPASYNC(dst + 13312 + j*208 + c*16, srcl + idx);
            }
            CPCOMMIT();
        }
        float hzv = hzp[i];
        char* ah = sm + SB_AH + anl*144 + ajh*64;
        char* al = sm + SB_AL + anl*144 + ajh*64;
#pragma unroll
        for (int g = 0; g < 4; g++) {
            uint32_t h[4], l[4];
            pack2h(hzv*tz[g*8+0], hzv*tz[g*8+1], h[0], l[0]);
            pack2h(hzv*tz[g*8+2], hzv*tz[g*8+3], h[1], l[1]);
            pack2h(hzv*tz[g*8+4], hzv*tz[g*8+5], h[2], l[2]);
            pack2h(hzv*tz[g*8+6], hzv*tz[g*8+7], h[3], l[3]);
            *(uint4*)(ah + g*16) = make_uint4(h[0], h[1], h[2], h[3]);
            *(uint4*)(al + g*16) = make_uint4(l[0], l[1], l[2], l[3]);
        }
        if (i < 63) { CPWAIT(1); } else { CPWAIT(0); }
        __syncthreads();
        uint32_t bhi = smb + SB_B0 + (i & 1) * SB_BUF;
        uint32_t blo = bhi + 13312;
#pragma unroll
        for (int kt = 0; kt < 4; kt++) {
            uint32_t bh[3][4], bl[3][4];
#pragma unroll
            for (int g = 0; g < 3; g++) {
                ldm_x4_t(bh[g], bhi + b_off + g*32 + kt*3328);
                ldm_x4_t(bl[g], blo + b_off + g*32 + kt*3328);
            }
#pragma unroll
            for (int mt = 0; mt < 2; mt++) {
                uint32_t a_hi[4], a_lo[4];
                ldm_x4(a_hi, a_base  + mt*2304 + kt*32);
                ldm_x4(a_lo, al_base + mt*2304 + kt*32);
#pragma unroll
                for (int lf = 0; lf < 6; lf++) {
                    float* d = acc[mt][lf];
                    int g = lf >> 1, hh = (lf & 1) * 2;
                    mma_f16(d, a_hi, &bh[g][hh]);
                    mma_f16(d, a_lo, &bh[g][hh]);
                    mma_f16(d, a_hi, &bl[g][hh]);
                }
            }
        }
        __syncthreads();
    }
    int rbase = n0 + wn*32 + (lane >> 2);
    int cbase = wl*48 + (lane & 3)*2;
#pragma unroll
    for (int mt = 0; mt < 2; mt++) {
#pragma unroll
        for (int lf = 0; lf < 6; lf++) {
            int r = rbase + mt*16;
            int c = cbase + lf*8;
            float* d = acc[mt][lf];
            *(float2*)&g_part[((size_t)k*NPAD + r)*128 + c]     = make_float2(d[0], d[1]);
            *(float2*)&g_part[((size_t)k*NPAD + r + 8)*128 + c] = make_float2(d[2], d[3]);
        }
    }
}

// ---------------- reduce split partials + bias -> logits -----------------------
__global__ void k_logits(const float* __restrict__ bb, float* __restrict__ out) {
    int g = blockIdx.x * 256 + threadIdx.x;
    if (g >= NTOT*NL) return;
    int n = g / NL, l = g % NL;
    float s = bb[l];
#pragma unroll
    for (int sp = 0; sp < NSPLIT; sp++)
        s += g_part[((size_t)sp*NPAD + n)*128 + l];
    out[1 + (size_t)n*NL + l] = s;
}

// ---------------- K_RISK_ALL: per-class risk + last-block total -----------------
__global__ void k_risk_all(const float* __restrict__ out_ro, const int* __restrict__ labels,
                           const float* __restrict__ pl, const float* __restrict__ po,
                           float* __restrict__ out) {
    int r = blockIdx.x;
    int tid = threadIdx.x;
    float s_neg = 0.f, s_pp = 0.f, s_pn = 0.f, c_pos = 0.f;
    for (int n = tid; n < NTOT; n += 256) {
        float l0 = out_ro[1 + (size_t)n*NL];
        float sc = out_ro[1 + (size_t)n*NL + (r+1)] - l0;
        bool pos = labels[(size_t)n*NL + (r+1)] == 1;
        float lp = 0.25f * (sc - 1.f) * (sc - 1.f);
        float ln = 0.25f * (-sc - 1.f) * (-sc - 1.f);
        if (pos) { c_pos += 1.f; s_pp += lp; s_pn += ln; }
        else     { s_neg += ln; }
    }
    __shared__ float red[4][256];
    red[0][tid] = s_neg; red[1][tid] = s_pp; red[2][tid] = s_pn; red[3][tid] = c_pos;
    __syncthreads();
    for (int st = 128; st > 0; st >>= 1) {
        if (tid < st) {
#pragma unroll
            for (int q = 0; q < 4; q++) red[q][tid] += red[q][tid + st];
        }
        __syncthreads();
    }
    __shared__ unsigned int s_last;
    if (tid == 0) {
        float cp = red[3][0], cn = (float)NTOT - cp;
        float sq_neg = (cn > 0.f) ? red[0][0] / fmaxf(cn, 1.f) : 0.f;
        float sq_pp  = (cp > 0.f) ? red[1][0] / fmaxf(cp, 1.f) : 0.f;
        float sq_pn  = (cp > 0.f) ? red[2][0] / fmaxf(cp, 1.f) : 0.f;
        float o = po[r], lq = pl[r];
        float w  = sqrtf((1.f - o) / o);
        float pu = (o - lq) / (1.f - lq);
        float risk1 = (1.f - o)/(1.f - pu)*sq_neg - (pu - pu*o)/(1.f - pu)*sq_pn;
        float risk2 = o * sq_pp * w;
        g_riskc[r] = (risk1 < 0.f) ? -risk1 : (risk1 + risk2);
        __threadfence();
        s_last = atomicAdd(&g_rdone, 1u);
    }
    __syncthreads();
    if (s_last == RELSn - 1) {
        __threadfence();
        __shared__ float rr[128];
        if (tid < 128) rr[tid] = (tid < RELSn) ? g_riskc[tid] : 0.f;
        __syncthreads();
        for (int st = 64; st > 0; st >>= 1) {
            if (tid < st) rr[tid] += rr[tid + st];
            __syncthreads();
        }
        if (tid == 0) { out[0] = rr[0]; g_rdone = 0; }
    }
}

// ---------------- launch ---------------------------------------------------------
extern "C" void kernel_launch(void* const* d_in, const int* in_sizes, int n_in,
                              void* d_out, int out_size) {
    const float* seq      = (const float*)d_in[0];
    const float* att      = (const float*)d_in[1];
    const int*   midx     = (const int*)  d_in[2];
    const float* mmask    = (const float*)d_in[3];
    const int*   hts      = (const int*)  d_in[4];
    const int*   labels   = (const int*)  d_in[5];
    const float* priors_l = (const float*)d_in[6];
    const float* priors_o = (const float*)d_in[7];
    const float* head_W   = (const float*)d_in[8];
    const float* head_b   = (const float*)d_in[9];
    const float* tail_W   = (const float*)d_in[10];
    const float* tail_b   = (const float*)d_in[11];
    const float* bil_W    = (const float*)d_in[12];
    const float* bil_b    = (const float*)d_in[13];
    float* out = (float*)d_out;

    cudaFuncSetAttribute(k_bilin_c96, cudaFuncAttributeMaxDynamicSharedMemorySize, SB_TOT);
    cudaFuncSetAttribute(k_rs_entU,   cudaFuncAttributeMaxDynamicSharedMemorySize, GEMM_SM);
    cudaFuncSetAttribute(k_rw_mma,    cudaFuncAttributeMaxDynamicSharedMemorySize, GEMM_SM);

    k_prep<<<4440, 256>>>(seq, att, midx, mmask, bil_W, head_W, tail_W);
    k_ht<<<NTOT, 256>>>(hts);
    k_rs_entU<<<168, 256, GEMM_SM>>>(head_W, tail_W);
    k_rw_mma<<<dim3(19, 12), 256, GEMM_SM>>>(hts, head_b, tail_b);
    k_bilin_c96<<<468, 256, SB_TOT>>>();
    k_logits<<<(NTOT*NL + 255)/256, 256>>>(bil_b, out);
    k_risk_all<<<RELSn, 256>>>(out, labels, priors_l, priors_o, out);
}

// round 13
// speedup vs baseline: 1.4839x; 1.4839x over previous
#include <cuda_runtime.h>
#include <cuda_bf16.h>
#include <cuda_fp16.h>
#include <math.h>
#include <stdint.h>

#define Bq    4
#define Hh    12
#define Cc    1024
#define Dd    768
#define Ee    30
#define Mm    8
#define Pp    600
#define NL    97
#define RELSn 96
#define EMBn  768
#define NTOT  2400   // B*P
#define NPAD  2560   // pad rows stay zero
#define NSPLIT 12    // k blocks

// ---------------- scratch (static device globals; no allocation) -------------
__device__ float g_ent_emb[Bq*Ee*Dd];          // [B,E,D]
__device__ float g_ent_att[Bq*Ee*Hh*Cc];       // [B,E,H,C]
__device__ float g_hz[NPAD*EMBn];              // rows >=2400 stay zero
__device__ float g_tz[NPAD*EMBn];
__device__ uint32_t g_wtf[768*3072];           // bil W fp16 hi: [blob][64 j][48 lpair]
__device__ uint32_t g_wtl[768*3072];           // bil W fp16 lo (residual)
__device__ float    g_w96[768*64];             // bil W col 96: [blob][j]
__device__ uint32_t g_ht_hi[Bq*640*512];       // ht_att bf16 pairs [b][640][512]
__device__ uint32_t g_ht_lo[Bq*640*512];
__device__ uint32_t g_seq_hi[Bq*Cc*384];       // seq bf16 pairs [b][1024][384]
__device__ uint32_t g_seq_lo[Bq*Cc*384];
__device__ uint32_t g_rs_hi[2432*384];         // rs bf16 pairs (pad rows zero)
__device__ uint32_t g_rs_lo[2432*384];
__device__ uint32_t g_wb_hi[768*768];          // [W_bot_head | W_bot_tail] pairs
__device__ uint32_t g_wb_lo[768*768];
__device__ float g_U[2*Bq*Ee*EMBn];            // ent_emb @ W_top (head, tail)
__device__ float g_part[NSPLIT*NPAD*128];      // split partial logits
__device__ float g_riskc[RELSn];
__device__ unsigned int g_rdone = 0;

// =================== helpers ===================================================
__device__ __forceinline__ uint32_t smem_u32(const void* p) {
    uint32_t a;
    asm("{ .reg .u64 t; cvta.to.shared.u64 t, %1; cvt.u32.u64 %0, t; }" : "=r"(a) : "l"(p));
    return a;
}
__device__ __forceinline__ void pack2(float p0, float p1, uint32_t& hi, uint32_t& lo) {
    uint32_t h;
    asm("cvt.rn.bf16x2.f32 %0, %1, %2;" : "=r"(h) : "f"(p1), "f"(p0));
    float h0 = __uint_as_float(h << 16);
    float h1 = __uint_as_float(h & 0xFFFF0000u);
    float l0 = p0 - h0, l1 = p1 - h1;
    uint32_t l;
    asm("cvt.rn.bf16x2.f32 %0, %1, %2;" : "=r"(l) : "f"(l1), "f"(l0));
    hi = h; lo = l;
}
__device__ __forceinline__ void pack2h(float p0, float p1, uint32_t& hi, uint32_t& lo) {
    __half2 h = __floats2half2_rn(p0, p1);
    float2 hf = __half22float2(h);
    __half2 l = __floats2half2_rn(p0 - hf.x, p1 - hf.y);
    hi = *(uint32_t*)&h;
    lo = *(uint32_t*)&l;
}
__device__ __forceinline__ void ldm_x4(uint32_t* r, uint32_t addr) {
    asm volatile("ldmatrix.sync.aligned.m8n8.x4.shared.b16 {%0,%1,%2,%3}, [%4];"
        : "=r"(r[0]), "=r"(r[1]), "=r"(r[2]), "=r"(r[3]) : "r"(addr));
}
__device__ __forceinline__ void ldm_x4_t(uint32_t* r, uint32_t addr) {
    asm volatile("ldmatrix.sync.aligned.m8n8.x4.trans.shared.b16 {%0,%1,%2,%3}, [%4];"
        : "=r"(r[0]), "=r"(r[1]), "=r"(r[2]), "=r"(r[3]) : "r"(addr));
}
__device__ __forceinline__ void mma_bf16(float* d, const uint32_t* a, const uint32_t* b) {
    asm volatile(
        "mma.sync.aligned.m16n8k16.row.col.f32.bf16.bf16.f32 "
        "{%0,%1,%2,%3}, {%4,%5,%6,%7}, {%8,%9}, {%0,%1,%2,%3};"
        : "+f"(d[0]), "+f"(d[1]), "+f"(d[2]), "+f"(d[3])
        : "r"(a[0]), "r"(a[1]), "r"(a[2]), "r"(a[3]), "r"(b[0]), "r"(b[1]));
}
__device__ __forceinline__ void mma_f16(float* d, const uint32_t* a, const uint32_t* b) {
    asm volatile(
        "mma.sync.aligned.m16n8k16.row.col.f32.f16.f16.f32 "
        "{%0,%1,%2,%3}, {%4,%5,%6,%7}, {%8,%9}, {%0,%1,%2,%3};"
        : "+f"(d[0]), "+f"(d[1]), "+f"(d[2]), "+f"(d[3])
        : "r"(a[0]), "r"(a[1]), "r"(a[2]), "r"(a[3]), "r"(b[0]), "r"(b[1]));
}
#define CPASYNC(dst, src) asm volatile("cp.async.cg.shared.global [%0], [%1], 16;" :: "r"(dst), "l"(src))
#define CPCOMMIT()        asm volatile("cp.async.commit_group;")
#define CPWAIT(n)         asm volatile("cp.async.wait_group %0;" :: "n"(n) : "memory")

// ---------------- K_PREP: fused ent_att | wsplit | ent_emb | wbsplit | seqsplit -
// blocks: [0,1440) ent_att | [1440,2208) wsplit | [2208,2328) ent_emb
//         [2328,2616) wbsplit | [2616,3384) seqsplit
__global__ __launch_bounds__(256) void k_prep(
    const float* __restrict__ seq, const float* __restrict__ att,
    const int* __restrict__ midx, const float* __restrict__ mmask,
    const float* __restrict__ bilW,
    const float* __restrict__ hW, const float* __restrict__ tW)
{
    int bid = blockIdx.x;
    int tid = threadIdx.x;
    __shared__ int   s_idx[Mm];
    __shared__ float s_w[Mm];

    if (bid < 1440) {
        int g  = bid;
        int h  = g % Hh;
        int be = g / Hh;
        int b  = be / Ee;
        if (tid < Mm) {
            s_idx[tid] = midx[be*Mm + tid] + 1;
            s_w[tid]   = mmask[be*Mm + tid];
        }
        __syncthreads();
        float cnt = 0.f;
#pragma unroll
        for (int m = 0; m < Mm; m++) cnt += s_w[m];
        float inv = 1.f / cnt;
        const float* base = att + ((size_t)b*Hh + h)*Cc*Cc;
        for (int c = tid; c < Cc; c += 256) {
            float s = 0.f;
#pragma unroll
            for (int m = 0; m < Mm; m++)
                s += s_w[m] * base[(size_t)s_idx[m]*Cc + c];
            g_ent_att[(size_t)g*Cc + c] = s * inv;
        }
    } else if (bid < 2208) {
        int blob = bid - 1440;
        int j = tid >> 2, lq = (tid & 3) * 24;
        size_t row = ((size_t)blob*64 + j) * NL;
        uint32_t* oh = g_wtf + ((size_t)blob*64 + j)*48 + (lq >> 1);
        uint32_t* ol = g_wtl + ((size_t)blob*64 + j)*48 + (lq >> 1);
#pragma unroll
        for (int q = 0; q < 12; q++) {
            int l0 = lq + q*2;
            float v0 = bilW[row + l0];
            float v1 = bilW[row + l0 + 1];
            uint32_t h, l;
            pack2h(v0, v1, h, l);
            oh[q] = h; ol[q] = l;
        }
        if ((tid & 3) == 0) g_w96[(size_t)blob*64 + j] = bilW[row + 96];
    } else if (bid < 2328) {
        int be = bid - 2208;
        int b  = be / Ee;
        if (tid < Mm) {
            s_idx[tid] = midx[be*Mm + tid] + 1;
            s_w[tid]   = mmask[be*Mm + tid];
        }
        __syncthreads();
        for (int d = tid; d < Dd; d += 256) {
            float xv[Mm];
            float mx = -1e30f;
#pragma unroll
            for (int m = 0; m < Mm; m++) {
                float x = seq[((size_t)b*Cc + s_idx[m])*Dd + d];
                xv[m] = x;
                if (s_w[m] > 0.f) mx = fmaxf(mx, x);
            }
            float s = 0.f;
#pragma unroll
            for (int m = 0; m < Mm; m++)
                if (s_w[m] > 0.f) s += s_w[m] * __expf(xv[m] - mx);
            g_ent_emb[(size_t)be*Dd + d] = __logf(s) + mx;
        }
    } else if (bid < 2616) {
        // wbsplit: 8 elems/thread; total 768*768
        int i0 = (bid - 2328)*2048 + tid*8;
#pragma unroll
        for (int q = 0; q < 8; q++) {
            int i = i0 + q;
            int kk = i / 768, c = i % 768;
            int c2 = c*2;
            const float* W = (c2 < 768) ? hW : tW;
            int col = (c2 < 768) ? c2 : (c2 - 768);
            size_t ro = (size_t)(768 + kk) * EMBn;
            uint32_t h, l;
            pack2(W[ro + col], W[ro + col + 1], h, l);
            g_wb_hi[i] = h; g_wb_lo[i] = l;
        }
    } else {
        // seqsplit: 8 elems/thread; total 4*1024*384
        int i0 = (bid - 2616)*2048 + tid*8;
#pragma unroll
        for (int q = 0; q < 8; q++) {
            int i = i0 + q;
            uint32_t h, l;
            pack2(seq[(size_t)i*2], seq[(size_t)i*2+1], h, l);
            g_seq_hi[i] = h; g_seq_lo[i] = l;
        }
    }
}

// ---------------- K_HT: ht_att -> bf16 hi/lo split ------------------------------
__global__ void k_ht(const int* __restrict__ hts) {
    int n = blockIdx.x;
    int b = n / Pp, p = n % Pp;
    int hi = hts[n*2 + 0], ti = hts[n*2 + 1];
    size_t hb = (size_t)(b*Ee + hi) * Hh * Cc;
    size_t tb = (size_t)(b*Ee + ti) * Hh * Cc;
    __shared__ float vals[Cc];
    __shared__ float red[256];
    float loc = 0.f;
    for (int c = threadIdx.x; c < Cc; c += 256) {
        float s = 0.f;
#pragma unroll
        for (int h = 0; h < Hh; h++)
            s += g_ent_att[hb + (size_t)h*Cc + c] * g_ent_att[tb + (size_t)h*Cc + c];
        s *= (1.f / Hh);
        vals[c] = s;
        loc += s;
    }
    red[threadIdx.x] = loc;
    __syncthreads();
    for (int st = 128; st > 0; st >>= 1) {
        if (threadIdx.x < st) red[threadIdx.x] += red[threadIdx.x + st];
        __syncthreads();
    }
    float invt = 1.f / (red[0] + 1e-5f);
    uint32_t* oh = g_ht_hi + ((size_t)b*640 + p)*512;
    uint32_t* ol = g_ht_lo + ((size_t)b*640 + p)*512;
    for (int c2 = threadIdx.x; c2 < 512; c2 += 256) {
        float v0 = vals[c2*2]   * invt;
        float v1 = vals[c2*2+1] * invt;
        uint32_t h, l;
        pack2(v0, v1, h, l);
        oh[c2] = h; ol[c2] = l;
    }
}

// ---------------- bf16x3 mma GEMM mainloop (128x128 tile, 256 thr, occ2) -------
#define GA_H 0
#define GA_L 18432
#define GB_H 36864
#define GB_L 54272
#define GEMM_SM 71680

__device__ __forceinline__ void gemm_main(float acc[4][4][4],
    const uint32_t* __restrict__ Ah, const uint32_t* __restrict__ Al,
    const uint32_t* __restrict__ Bh, const uint32_t* __restrict__ Bl,
    int K, int N, int m0, int n0)
{
    extern __shared__ char sm[];
    uint32_t smb = smem_u32(sm);
    int tid = threadIdx.x, lane = tid & 31, wid = tid >> 5;
    int lda32 = K >> 1, ldb32 = N >> 1;
    int wn = wid >> 2, wl = wid & 3, lq = lane & 15, lh = lane >> 4;
    uint32_t a_base  = smb + GA_H + (wn*64 + lq)*144 + lh*16;
    uint32_t al_base = a_base + (GA_L - GA_H);
    uint32_t b_base  = smb + GB_H + lq*272 + (wl*64 + lh*16);
    uint32_t bl_base = b_base + (GB_L - GB_H);
    for (int kc = 0; kc < K; kc += 64) {
#pragma unroll
        for (int rep = 0; rep < 4; rep++) {
            int idx = tid + rep*256;
            int row = idx >> 3, c4 = idx & 7;
            size_t go = (size_t)(m0 + row)*lda32 + (kc >> 1) + c4*4;
            CPASYNC(smb + GA_H + row*144 + c4*16, (const uint4*)&Ah[go]);
            CPASYNC(smb + GA_L + row*144 + c4*16, (const uint4*)&Al[go]);
        }
#pragma unroll
        for (int rep = 0; rep < 4; rep++) {
            int idx = tid + rep*256;
            int row = idx >> 4, c4 = idx & 15;
            size_t go = (size_t)(kc + row)*ldb32 + (n0 >> 1) + c4*4;
            CPASYNC(smb + GB_H + row*272 + c4*16, (const uint4*)&Bh[go]);
            CPASYNC(smb + GB_L + row*272 + c4*16, (const uint4*)&Bl[go]);
        }
        CPCOMMIT();
        CPWAIT(0);
        __syncthreads();
#pragma unroll
        for (int kt = 0; kt < 4; kt++) {
            uint32_t a_hi[4][4], a_lo[4][4];
#pragma unroll
            for (int mt = 0; mt < 4; mt++) {
                ldm_x4(a_hi[mt], a_base  + mt*2304 + kt*32);
                ldm_x4(a_lo[mt], al_base + mt*2304 + kt*32);
            }
#pragma unroll
            for (int lt = 0; lt < 2; lt++) {
                uint32_t b_hi[4], b_lo[4];
                ldm_x4_t(b_hi, b_base  + kt*4352 + lt*32);
                ldm_x4_t(b_lo, bl_base + kt*4352 + lt*32);
#pragma unroll
                for (int mt = 0; mt < 4; mt++) {
#pragma unroll
                    for (int f = 0; f < 2; f++) {
                        float* d = acc[mt][lt*2 + f];
                        mma_bf16(d, a_hi[mt], &b_hi[f*2]);
                        mma_bf16(d, a_lo[mt], &b_hi[f*2]);
                        mma_bf16(d, a_hi[mt], &b_lo[f*2]);
                    }
                }
            }
        }
        __syncthreads();
    }
}

// ---------------- K_RS_ENTU: fused rs GEMM (120 blocks) + entU (48 blocks) -----
__global__ __launch_bounds__(256, 2) void k_rs_entU(const float* __restrict__ hW,
                                                    const float* __restrict__ tW) {
    extern __shared__ char sm[];
    int bid = blockIdx.x;
    int tid = threadIdx.x;
    if (bid < 120) {
        int b = bid / 30;
        int rem = bid % 30;
        int m0 = (rem % 5) * 128, n0 = (rem / 5) * 128;
        float acc[4][4][4] = {};
        gemm_main(acc,
                  g_ht_hi + (size_t)b*640*512, g_ht_lo + (size_t)b*640*512,
                  g_seq_hi + (size_t)b*Cc*384, g_seq_lo + (size_t)b*Cc*384,
                  Cc, Dd, m0, n0);
        int lane = tid & 31, wid = tid >> 5;
        int wn = wid >> 2, wl = wid & 3;
        int rbase = m0 + wn*64 + (lane >> 2);
        int cbase = n0 + wl*32 + (lane & 3)*2;
#pragma unroll
        for (int mt = 0; mt < 4; mt++) {
#pragma unroll
            for (int lf = 0; lf < 4; lf++) {
                int r = rbase + mt*16;
                int cp = (cbase + lf*8) >> 1;
                float* d = acc[mt][lf];
                if (r < Pp) {
                    uint32_t h, l;
                    pack2(d[0], d[1], h, l);
                    g_rs_hi[((size_t)(b*Pp + r))*384 + cp] = h;
                    g_rs_lo[((size_t)(b*Pp + r))*384 + cp] = l;
                }
                if (r + 8 < Pp) {
                    uint32_t h, l;
                    pack2(d[2], d[3], h, l);
                    g_rs_hi[((size_t)(b*Pp + r + 8))*384 + cp] = h;
                    g_rs_lo[((size_t)(b*Pp + r + 8))*384 + cp] = l;
                }
            }
        }
    } else {
        // ---- entU: ent_emb @ W_top (SIMT)
        int idx = bid - 120;
        int mb = (idx & 1) * 64;
        int nb = ((idx >> 1) % 12) * 64;
        int s  = idx / 24;
        const float* W = s ? tW : hW;
        float* As = (float*)sm;
        float* Bs = (float*)(sm + 4096);
        int tm = tid >> 4, tn = tid & 15;
        int lm = tid & 63, lk4 = (tid >> 6) << 2;
        float acc[4][4] = {};
        for (int kc = 0; kc < Dd; kc += 16) {
            float4 av = make_float4(0.f,0.f,0.f,0.f);
            int m = mb + lm;
            if (m < Bq*Ee) av = *(const float4*)&g_ent_emb[(size_t)m*Dd + kc + lk4];
            As[(lk4+0)*64+lm] = av.x; As[(lk4+1)*64+lm] = av.y;
            As[(lk4+2)*64+lm] = av.z; As[(lk4+3)*64+lm] = av.w;
#pragma unroll
            for (int r = 0; r < 4; r++) {
                int kk = lk4 + r;
                Bs[kk*64+lm] = W[(size_t)(kc+kk)*EMBn + nb + lm];
            }
            __syncthreads();
#pragma unroll
            for (int kk = 0; kk < 16; kk++) {
                float4 a4 = *(const float4*)&As[kk*64 + tm*4];
                float4 b4 = *(const float4*)&Bs[kk*64 + tn*4];
                acc[0][0] += a4.x*b4.x; acc[0][1] += a4.x*b4.y; acc[0][2] += a4.x*b4.z; acc[0][3] += a4.x*b4.w;
                acc[1][0] += a4.y*b4.x; acc[1][1] += a4.y*b4.y; acc[1][2] += a4.y*b4.z; acc[1][3] += a4.y*b4.w;
                acc[2][0] += a4.z*b4.x; acc[2][1] += a4.z*b4.y; acc[2][2] += a4.z*b4.z; acc[2][3] += a4.z*b4.w;
                acc[3][0] += a4.w*b4.x; acc[3][1] += a4.w*b4.y; acc[3][2] += a4.w*b4.z; acc[3][3] += a4.w*b4.w;
            }
            __syncthreads();
        }
#pragma unroll
        for (int a = 0; a < 4; a++) {
            int m = mb + tm*4 + a;
            if (m < Bq*Ee)
                *(float4*)&g_U[((size_t)s*Bq*Ee + m)*EMBn + nb + tn*4] =
                    make_float4(acc[a][0], acc[a][1], acc[a][2], acc[a][3]);
        }
    }
}

// ---------------- K_RW: rs @ [Wbh|Wbt]; fused U-gather + bias + tanh ------------
__global__ __launch_bounds__(256, 2) void k_rw_mma(const int* __restrict__ hts,
                                                   const float* __restrict__ hb,
                                                   const float* __restrict__ tb) {
    int m0 = blockIdx.x * 128, n0 = blockIdx.y * 128;
    float acc[4][4][4] = {};
    gemm_main(acc, g_rs_hi, g_rs_lo, g_wb_hi, g_wb_lo, Dd, 1536, m0, n0);
    int tid = threadIdx.x, lane = tid & 31, wid = tid >> 5;
    int wn = wid >> 2, wl = wid & 3;
    int rbase = m0 + wn*64 + (lane >> 2);
    int cbase = n0 + wl*32 + (lane & 3)*2;
#pragma unroll
    for (int mt = 0; mt < 4; mt++) {
#pragma unroll
        for (int rr = 0; rr < 2; rr++) {
            int r = rbase + mt*16 + rr*8;
            if (r >= NTOT) continue;
            int b = r / Pp;
            int e0 = hts[r*2 + 0], e1 = hts[r*2 + 1];
#pragma unroll
            for (int lf = 0; lf < 4; lf++) {
                int c = cbase + lf*8;
                int s = (c >= 768);
                int cc = c - (s ? 768 : 0);
                int e = s ? e1 : e0;
                const float* Ur = g_U + ((size_t)(s*Bq*Ee + b*Ee + e))*EMBn + cc;
                const float* bi = (s ? tb : hb) + cc;
                float* dst = (s ? g_tz : g_hz) + (size_t)r*EMBn + cc;
                float* d = acc[mt][lf];
                float2 o;
                o.x = tanhf(d[rr*2 + 0] + Ur[0] + bi[0]);
                o.y = tanhf(d[rr*2 + 1] + Ur[1] + bi[1]);
                *(float2*)dst = o;
            }
        }
    }
}

// ---------------- K_BILIN_C96: fp16x3 bilinear (240 @128-row, occ2) + c96 (228) -
#define SB_AH 0          // A hi: 128 x 144B
#define SB_AL 18432      // A lo
#define SB_B0 36864      // B stages: 2 x (hi 13312 + lo 13312)
#define SB_BUF 26624
#define SB_TOT 90112

__global__ __launch_bounds__(256, 2) void k_bilin_c96() {
    extern __shared__ char sm[];
    uint32_t smb = smem_u32(sm);
    int bid = blockIdx.x;
    int tid = threadIdx.x, lane = tid & 31, wid = tid >> 5;

    if (bid >= 240) {
        // ---- c96: exact fp32 column 96 (128-row tiles)
        int idx = bid - 240;
        int n0 = (idx % 19) * 128, k = idx / 19;
        float* Ws  = (float*)sm;          // [64][64]
        float* hzs = Ws + 4096;           // [128][65]
        float* tzs = hzs + 128*65;        // [128][65]
        for (int e = tid; e < 4096; e += 256)
            Ws[e] = g_w96[(size_t)k*4096 + e];
        for (int e = tid; e < 128*64; e += 256) {
            int r = e >> 6, c = e & 63;
            int n = n0 + r;
            float hv = 0.f, tv = 0.f;
            if (n < NTOT) {
                hv = g_hz[(size_t)n*EMBn + k*64 + c];
                tv = g_tz[(size_t)n*EMBn + k*64 + c];
            }
            hzs[r*65 + c] = hv;
            tzs[r*65 + c] = tv;
        }
        __syncthreads();
        if (tid < 128) {
            float tzr[64];
#pragma unroll
            for (int j = 0; j < 64; j++) tzr[j] = tzs[tid*65 + j];
            float acc = 0.f;
            for (int i = 0; i < 64; i++) {
                const float4* wr = (const float4*)&Ws[i*64];
                float s = 0.f;
#pragma unroll
                for (int j4 = 0; j4 < 16; j4++) {
                    float4 w = wr[j4];
                    s += w.x*tzr[j4*4] + w.y*tzr[j4*4+1] + w.z*tzr[j4*4+2] + w.w*tzr[j4*4+3];
                }
                acc += hzs[tid*65 + i] * s;
            }
            int n = n0 + tid;
            if (n < NTOT) g_part[((size_t)k*NPAD + n)*128 + 96] = acc;
        }
        return;
    }

    // ---- bilinear: 128-row tile, wn4 x wl2
    int n0 = (bid % 20) * 128, k = bid / 20;
    int anl = tid >> 1, ajh = tid & 1;

    float tz[32];
    {
        const float* tzp = g_tz + (size_t)(n0 + anl)*EMBn + k*64 + ajh*32;
#pragma unroll
        for (int j = 0; j < 32; j++) tz[j] = tzp[j];
    }
    const float* hzp = g_hz + (size_t)(n0 + anl)*EMBn + k*64;

    int wn = wid >> 1, wl = wid & 1;
    int lq = lane & 15, lh = lane >> 4;
    uint32_t a_base  = smb + SB_AH + (wn*32 + lq)*144 + lh*16;
    uint32_t al_base = a_base + (SB_AL - SB_AH);
    uint32_t b_off   = lq*208 + wl*96 + lh*16;

    {
        const uint4* srch = ((const uint4*)g_wtf) + (size_t)(k*64)*768;
        const uint4* srcl = ((const uint4*)g_wtl) + (size_t)(k*64)*768;
#pragma unroll
        for (int rep = 0; rep < 3; rep++) {
            int idx = tid + rep*256;
            int j = idx / 12, c = idx % 12;
            CPASYNC(smb + SB_B0 + j*208 + c*16, srch + idx);
            CPASYNC(smb + SB_B0 + 13312 + j*208 + c*16, srcl + idx);
        }
        CPCOMMIT();
    }

    float acc[2][6][4] = {};

    for (int i = 0; i < 64; i++) {
        if (i < 63) {
            size_t blob = (size_t)(k*64 + i + 1) * 768;
            const uint4* srch = ((const uint4*)g_wtf) + blob;
            const uint4* srcl = ((const uint4*)g_wtl) + blob;
            uint32_t dst = smb + SB_B0 + ((i + 1) & 1) * SB_BUF;
#pragma unroll
            for (int rep = 0; rep < 3; rep++) {
                int idx = tid + rep*256;
                int j = idx / 12, c = idx % 12;
                CPASYNC(dst + j*208 + c*16, srch + idx);
                CPASYNC(dst + 13312 + j*208 + c*16, srcl + idx);
            }
            CPCOMMIT();
        }
        float hzv = hzp[i];
        char* ah = sm + SB_AH + anl*144 + ajh*64;
        char* al = sm + SB_AL + anl*144 + ajh*64;
#pragma unroll
        for (int g = 0; g < 4; g++) {
            uint32_t h[4], l[4];
            pack2h(hzv*tz[g*8+0], hzv*tz[g*8+1], h[0], l[0]);
            pack2h(hzv*tz[g*8+2], hzv*tz[g*8+3], h[1], l[1]);
            pack2h(hzv*tz[g*8+4], hzv*tz[g*8+5], h[2], l[2]);
            pack2h(hzv*tz[g*8+6], hzv*tz[g*8+7], h[3], l[3]);
            *(uint4*)(ah + g*16) = make_uint4(h[0], h[1], h[2], h[3]);
            *(uint4*)(al + g*16) = make_uint4(l[0], l[1], l[2], l[3]);
        }
        if (i < 63) { CPWAIT(1); } else { CPWAIT(0); }
        __syncthreads();
        uint32_t bhi = smb + SB_B0 + (i & 1) * SB_BUF;
        uint32_t blo = bhi + 13312;
#pragma unroll
        for (int kt = 0; kt < 4; kt++) {
            uint32_t bh[3][4], bl[3][4];
#pragma unroll
            for (int g = 0; g < 3; g++) {
                ldm_x4_t(bh[g], bhi + b_off + g*32 + kt*3328);
                ldm_x4_t(bl[g], blo + b_off + g*32 + kt*3328);
            }
#pragma unroll
            for (int mt = 0; mt < 2; mt++) {
                uint32_t a_hi[4], a_lo[4];
                ldm_x4(a_hi, a_base  + mt*2304 + kt*32);
                ldm_x4(a_lo, al_base + mt*2304 + kt*32);
#pragma unroll
                for (int lf = 0; lf < 6; lf++) {
                    float* d = acc[mt][lf];
                    int g = lf >> 1, hh = (lf & 1) * 2;
                    mma_f16(d, a_hi, &bh[g][hh]);
                    mma_f16(d, a_lo, &bh[g][hh]);
                    mma_f16(d, a_hi, &bl[g][hh]);
                }
            }
        }
        __syncthreads();
    }
    int rbase = n0 + wn*32 + (lane >> 2);
    int cbase = wl*48 + (lane & 3)*2;
#pragma unroll
    for (int mt = 0; mt < 2; mt++) {
#pragma unroll
        for (int lf = 0; lf < 6; lf++) {
            int r = rbase + mt*16;
            int c = cbase + lf*8;
            float* d = acc[mt][lf];
            *(float2*)&g_part[((size_t)k*NPAD + r)*128 + c]     = make_float2(d[0], d[1]);
            *(float2*)&g_part[((size_t)k*NPAD + r + 8)*128 + c] = make_float2(d[2], d[3]);
        }
    }
}

// ---------------- reduce split partials + bias -> logits -----------------------
__global__ void k_logits(const float* __restrict__ bb, float* __restrict__ out) {
    int g = blockIdx.x * 256 + threadIdx.x;
    if (g >= NTOT*NL) return;
    int n = g / NL, l = g % NL;
    float s = bb[l];
#pragma unroll
    for (int sp = 0; sp < NSPLIT; sp++)
        s += g_part[((size_t)sp*NPAD + n)*128 + l];
    out[1 + (size_t)n*NL + l] = s;
}

// ---------------- K_RISK_ALL: per-class risk + last-block total -----------------
__global__ void k_risk_all(const float* __restrict__ out_ro, const int* __restrict__ labels,
                           const float* __restrict__ pl, const float* __restrict__ po,
                           float* __restrict__ out) {
    int r = blockIdx.x;
    int tid = threadIdx.x;
    float s_neg = 0.f, s_pp = 0.f, s_pn = 0.f, c_pos = 0.f;
    for (int n = tid; n < NTOT; n += 256) {
        float l0 = out_ro[1 + (size_t)n*NL];
        float sc = out_ro[1 + (size_t)n*NL + (r+1)] - l0;
        bool pos = labels[(size_t)n*NL + (r+1)] == 1;
        float lp = 0.25f * (sc - 1.f) * (sc - 1.f);
        float ln = 0.25f * (-sc - 1.f) * (-sc - 1.f);
        if (pos) { c_pos += 1.f; s_pp += lp; s_pn += ln; }
        else     { s_neg += ln; }
    }
    __shared__ float red[4][256];
    red[0][tid] = s_neg; red[1][tid] = s_pp; red[2][tid] = s_pn; red[3][tid] = c_pos;
    __syncthreads();
    for (int st = 128; st > 0; st >>= 1) {
        if (tid < st) {
#pragma unroll
            for (int q = 0; q < 4; q++) red[q][tid] += red[q][tid + st];
        }
        __syncthreads();
    }
    __shared__ unsigned int s_last;
    if (tid == 0) {
        float cp = red[3][0], cn = (float)NTOT - cp;
        float sq_neg = (cn > 0.f) ? red[0][0] / fmaxf(cn, 1.f) : 0.f;
        float sq_pp  = (cp > 0.f) ? red[1][0] / fmaxf(cp, 1.f) : 0.f;
        float sq_pn  = (cp > 0.f) ? red[2][0] / fmaxf(cp, 1.f) : 0.f;
        float o = po[r], lq = pl[r];
        float w  = sqrtf((1.f - o) / o);
        float pu = (o - lq) / (1.f - lq);
        float risk1 = (1.f - o)/(1.f - pu)*sq_neg - (pu - pu*o)/(1.f - pu)*sq_pn;
        float risk2 = o * sq_pp * w;
        g_riskc[r] = (risk1 < 0.f) ? -risk1 : (risk1 + risk2);
        __threadfence();
        s_last = atomicAdd(&g_rdone, 1u);
    }
    __syncthreads();
    if (s_last == RELSn - 1) {
        __threadfence();
        __shared__ float rr[128];
        if (tid < 128) rr[tid] = (tid < RELSn) ? g_riskc[tid] : 0.f;
        __syncthreads();
        for (int st = 64; st > 0; st >>= 1) {
            if (tid < st) rr[tid] += rr[tid + st];
            __syncthreads();
        }
        if (tid == 0) { out[0] = rr[0]; g_rdone = 0; }
    }
}

// ---------------- launch ---------------------------------------------------------
extern "C" void kernel_launch(void* const* d_in, const int* in_sizes, int n_in,
                              void* d_out, int out_size) {
    const float* seq      = (const float*)d_in[0];
    const float* att      = (const float*)d_in[1];
    const int*   midx     = (const int*)  d_in[2];
    const float* mmask    = (const float*)d_in[3];
    const int*   hts      = (const int*)  d_in[4];
    const int*   labels   = (const int*)  d_in[5];
    const float* priors_l = (const float*)d_in[6];
    const float* priors_o = (const float*)d_in[7];
    const float* head_W   = (const float*)d_in[8];
    const float* head_b   = (const float*)d_in[9];
    const float* tail_W   = (const float*)d_in[10];
    const float* tail_b   = (const float*)d_in[11];
    const float* bil_W    = (const float*)d_in[12];
    const float* bil_b    = (const float*)d_in[13];
    float* out = (float*)d_out;

    cudaFuncSetAttribute(k_bilin_c96, cudaFuncAttributeMaxDynamicSharedMemorySize, SB_TOT);
    cudaFuncSetAttribute(k_rs_entU,   cudaFuncAttributeMaxDynamicSharedMemorySize, GEMM_SM);
    cudaFuncSetAttribute(k_rw_mma,    cudaFuncAttributeMaxDynamicSharedMemorySize, GEMM_SM);

    k_prep<<<3384, 256>>>(seq, att, midx, mmask, bil_W, head_W, tail_W);
    k_ht<<<NTOT, 256>>>(hts);
    k_rs_entU<<<168, 256, GEMM_SM>>>(head_W, tail_W);
    k_rw_mma<<<dim3(19, 12), 256, GEMM_SM>>>(hts, head_b, tail_b);
    k_bilin_c96<<<468, 256, SB_TOT>>>();
    k_logits<<<(NTOT*NL + 255)/256, 256>>>(bil_b, out);
    k_risk_all<<<RELSn, 256>>>(out, labels, priors_l, priors_o, out);
}

// round 14
// speedup vs baseline: 1.4894x; 1.0037x over previous
#include <cuda_runtime.h>
#include <cuda_bf16.h>
#include <cuda_fp16.h>
#include <math.h>
#include <stdint.h>

#define Bq    4
#define Hh    12
#define Cc    1024
#define Dd    768
#define Ee    30
#define Mm    8
#define Pp    600
#define NL    97
#define RELSn 96
#define EMBn  768
#define NTOT  2400   // B*P
#define NPAD  2560   // pad rows stay zero
#define NSPLIT 12    // k blocks

// ---------------- scratch (static device globals; no allocation) -------------
__device__ float g_ent_emb[Bq*Ee*Dd];          // [B,E,D]
__device__ float g_ent_att[Bq*Ee*Hh*Cc];       // [B,E,H,C]
__device__ float g_hz[NPAD*EMBn];              // rows >=2400 stay zero
__device__ float g_tz[NPAD*EMBn];
__device__ uint32_t g_wtf[768*3072];           // bil W fp16 hi: [blob][64 j][48 lpair]
__device__ uint32_t g_wtl[768*3072];           // bil W fp16 lo (residual)
__device__ float    g_w96[768*64];             // bil W col 96: [blob][j]
__device__ uint32_t g_ht_hi[Bq*640*512];       // ht_att bf16 pairs [b][640][512]
__device__ uint32_t g_ht_lo[Bq*640*512];
__device__ uint32_t g_seq_hi[Bq*Cc*384];       // seq bf16 pairs [b][1024][384]
__device__ uint32_t g_seq_lo[Bq*Cc*384];
__device__ uint32_t g_rs_hi[2432*384];         // rs bf16 pairs (pad rows zero)
__device__ uint32_t g_rs_lo[2432*384];
__device__ uint32_t g_wb_hi[768*768];          // [W_bot_head | W_bot_tail] pairs
__device__ uint32_t g_wb_lo[768*768];
__device__ float g_U[2*Bq*Ee*EMBn];            // ent_emb @ W_top (head, tail)
__device__ float g_part[NSPLIT*NPAD*128];      // split partial logits
__device__ float g_riskc[RELSn];
__device__ unsigned int g_rdone = 0;

// =================== helpers ===================================================
__device__ __forceinline__ uint32_t smem_u32(const void* p) {
    uint32_t a;
    asm("{ .reg .u64 t; cvta.to.shared.u64 t, %1; cvt.u32.u64 %0, t; }" : "=r"(a) : "l"(p));
    return a;
}
__device__ __forceinline__ void pack2(float p0, float p1, uint32_t& hi, uint32_t& lo) {
    uint32_t h;
    asm("cvt.rn.bf16x2.f32 %0, %1, %2;" : "=r"(h) : "f"(p1), "f"(p0));
    float h0 = __uint_as_float(h << 16);
    float h1 = __uint_as_float(h & 0xFFFF0000u);
    float l0 = p0 - h0, l1 = p1 - h1;
    uint32_t l;
    asm("cvt.rn.bf16x2.f32 %0, %1, %2;" : "=r"(l) : "f"(l1), "f"(l0));
    hi = h; lo = l;
}
__device__ __forceinline__ void pack2h(float p0, float p1, uint32_t& hi, uint32_t& lo) {
    __half2 h = __floats2half2_rn(p0, p1);
    float2 hf = __half22float2(h);
    __half2 l = __floats2half2_rn(p0 - hf.x, p1 - hf.y);
    hi = *(uint32_t*)&h;
    lo = *(uint32_t*)&l;
}
__device__ __forceinline__ void ldm_x4(uint32_t* r, uint32_t addr) {
    asm volatile("ldmatrix.sync.aligned.m8n8.x4.shared.b16 {%0,%1,%2,%3}, [%4];"
        : "=r"(r[0]), "=r"(r[1]), "=r"(r[2]), "=r"(r[3]) : "r"(addr));
}
__device__ __forceinline__ void ldm_x4_t(uint32_t* r, uint32_t addr) {
    asm volatile("ldmatrix.sync.aligned.m8n8.x4.trans.shared.b16 {%0,%1,%2,%3}, [%4];"
        : "=r"(r[0]), "=r"(r[1]), "=r"(r[2]), "=r"(r[3]) : "r"(addr));
}
__device__ __forceinline__ void mma_bf16(float* d, const uint32_t* a, const uint32_t* b) {
    asm volatile(
        "mma.sync.aligned.m16n8k16.row.col.f32.bf16.bf16.f32 "
        "{%0,%1,%2,%3}, {%4,%5,%6,%7}, {%8,%9}, {%0,%1,%2,%3};"
        : "+f"(d[0]), "+f"(d[1]), "+f"(d[2]), "+f"(d[3])
        : "r"(a[0]), "r"(a[1]), "r"(a[2]), "r"(a[3]), "r"(b[0]), "r"(b[1]));
}
__device__ __forceinline__ void mma_f16(float* d, const uint32_t* a, const uint32_t* b) {
    asm volatile(
        "mma.sync.aligned.m16n8k16.row.col.f32.f16.f16.f32 "
        "{%0,%1,%2,%3}, {%4,%5,%6,%7}, {%8,%9}, {%0,%1,%2,%3};"
        : "+f"(d[0]), "+f"(d[1]), "+f"(d[2]), "+f"(d[3])
        : "r"(a[0]), "r"(a[1]), "r"(a[2]), "r"(a[3]), "r"(b[0]), "r"(b[1]));
}
#define CPASYNC(dst, src) asm volatile("cp.async.cg.shared.global [%0], [%1], 16;" :: "r"(dst), "l"(src))
#define CPCOMMIT()        asm volatile("cp.async.commit_group;")
#define CPWAIT(n)         asm volatile("cp.async.wait_group %0;" :: "n"(n) : "memory")

// ---------------- K_PREP: fused ent_att | wsplit | ent_emb | wbsplit | seqsplit -
// blocks: [0,1440) ent_att | [1440,2208) wsplit | [2208,2328) ent_emb
//         [2328,2616) wbsplit | [2616,3384) seqsplit
__global__ __launch_bounds__(256) void k_prep(
    const float* __restrict__ seq, const float* __restrict__ att,
    const int* __restrict__ midx, const float* __restrict__ mmask,
    const float* __restrict__ bilW,
    const float* __restrict__ hW, const float* __restrict__ tW)
{
    int bid = blockIdx.x;
    int tid = threadIdx.x;
    __shared__ int   s_idx[Mm];
    __shared__ float s_w[Mm];

    if (bid < 1440) {
        int g  = bid;
        int h  = g % Hh;
        int be = g / Hh;
        int b  = be / Ee;
        if (tid < Mm) {
            s_idx[tid] = midx[be*Mm + tid] + 1;
            s_w[tid]   = mmask[be*Mm + tid];
        }
        __syncthreads();
        float cnt = 0.f;
#pragma unroll
        for (int m = 0; m < Mm; m++) cnt += s_w[m];
        float inv = 1.f / cnt;
        const float* base = att + ((size_t)b*Hh + h)*Cc*Cc;
        for (int c = tid; c < Cc; c += 256) {
            float s = 0.f;
#pragma unroll
            for (int m = 0; m < Mm; m++)
                s += s_w[m] * base[(size_t)s_idx[m]*Cc + c];
            g_ent_att[(size_t)g*Cc + c] = s * inv;
        }
    } else if (bid < 2208) {
        int blob = bid - 1440;
        int j = tid >> 2, lq = (tid & 3) * 24;
        size_t row = ((size_t)blob*64 + j) * NL;
        uint32_t* oh = g_wtf + ((size_t)blob*64 + j)*48 + (lq >> 1);
        uint32_t* ol = g_wtl + ((size_t)blob*64 + j)*48 + (lq >> 1);
#pragma unroll
        for (int q = 0; q < 12; q++) {
            int l0 = lq + q*2;
            float v0 = bilW[row + l0];
            float v1 = bilW[row + l0 + 1];
            uint32_t h, l;
            pack2h(v0, v1, h, l);
            oh[q] = h; ol[q] = l;
        }
        if ((tid & 3) == 0) g_w96[(size_t)blob*64 + j] = bilW[row + 96];
    } else if (bid < 2328) {
        int be = bid - 2208;
        int b  = be / Ee;
        if (tid < Mm) {
            s_idx[tid] = midx[be*Mm + tid] + 1;
            s_w[tid]   = mmask[be*Mm + tid];
        }
        __syncthreads();
        for (int d = tid; d < Dd; d += 256) {
            float xv[Mm];
            float mx = -1e30f;
#pragma unroll
            for (int m = 0; m < Mm; m++) {
                float x = seq[((size_t)b*Cc + s_idx[m])*Dd + d];
                xv[m] = x;
                if (s_w[m] > 0.f) mx = fmaxf(mx, x);
            }
            float s = 0.f;
#pragma unroll
            for (int m = 0; m < Mm; m++)
                if (s_w[m] > 0.f) s += s_w[m] * __expf(xv[m] - mx);
            g_ent_emb[(size_t)be*Dd + d] = __logf(s) + mx;
        }
    } else if (bid < 2616) {
        // wbsplit: 8 elems/thread; total 768*768
        int i0 = (bid - 2328)*2048 + tid*8;
#pragma unroll
        for (int q = 0; q < 8; q++) {
            int i = i0 + q;
            int kk = i / 768, c = i % 768;
            int c2 = c*2;
            const float* W = (c2 < 768) ? hW : tW;
            int col = (c2 < 768) ? c2 : (c2 - 768);
            size_t ro = (size_t)(768 + kk) * EMBn;
            uint32_t h, l;
            pack2(W[ro + col], W[ro + col + 1], h, l);
            g_wb_hi[i] = h; g_wb_lo[i] = l;
        }
    } else {
        // seqsplit: 8 elems/thread; total 4*1024*384
        int i0 = (bid - 2616)*2048 + tid*8;
#pragma unroll
        for (int q = 0; q < 8; q++) {
            int i = i0 + q;
            uint32_t h, l;
            pack2(seq[(size_t)i*2], seq[(size_t)i*2+1], h, l);
            g_seq_hi[i] = h; g_seq_lo[i] = l;
        }
    }
}

// ---------------- K_HT: ht_att -> bf16 hi/lo split ------------------------------
__global__ void k_ht(const int* __restrict__ hts) {
    int n = blockIdx.x;
    int b = n / Pp, p = n % Pp;
    int hi = hts[n*2 + 0], ti = hts[n*2 + 1];
    size_t hb = (size_t)(b*Ee + hi) * Hh * Cc;
    size_t tb = (size_t)(b*Ee + ti) * Hh * Cc;
    __shared__ float vals[Cc];
    __shared__ float red[256];
    float loc = 0.f;
    for (int c = threadIdx.x; c < Cc; c += 256) {
        float s = 0.f;
#pragma unroll
        for (int h = 0; h < Hh; h++)
            s += g_ent_att[hb + (size_t)h*Cc + c] * g_ent_att[tb + (size_t)h*Cc + c];
        s *= (1.f / Hh);
        vals[c] = s;
        loc += s;
    }
    red[threadIdx.x] = loc;
    __syncthreads();
    for (int st = 128; st > 0; st >>= 1) {
        if (threadIdx.x < st) red[threadIdx.x] += red[threadIdx.x + st];
        __syncthreads();
    }
    float invt = 1.f / (red[0] + 1e-5f);
    uint32_t* oh = g_ht_hi + ((size_t)b*640 + p)*512;
    uint32_t* ol = g_ht_lo + ((size_t)b*640 + p)*512;
    for (int c2 = threadIdx.x; c2 < 512; c2 += 256) {
        float v0 = vals[c2*2]   * invt;
        float v1 = vals[c2*2+1] * invt;
        uint32_t h, l;
        pack2(v0, v1, h, l);
        oh[c2] = h; ol[c2] = l;
    }
}

// ---------------- bf16x3 mma GEMM mainloop (128x128 tile, 256 thr, occ2) -------
// plain LDG->STS staging (R11 config; cp.async regressed here)
#define GA_H 0
#define GA_L 18432
#define GB_H 36864
#define GB_L 54272
#define GEMM_SM 71680

__device__ __forceinline__ void gemm_main(float acc[4][4][4],
    const uint32_t* __restrict__ Ah, const uint32_t* __restrict__ Al,
    const uint32_t* __restrict__ Bh, const uint32_t* __restrict__ Bl,
    int K, int N, int m0, int n0)
{
    extern __shared__ char sm[];
    uint32_t smb = smem_u32(sm);
    int tid = threadIdx.x, lane = tid & 31, wid = tid >> 5;
    int lda32 = K >> 1, ldb32 = N >> 1;
    int wn = wid >> 2, wl = wid & 3, lq = lane & 15, lh = lane >> 4;
    uint32_t a_base  = smb + GA_H + (wn*64 + lq)*144 + lh*16;
    uint32_t al_base = a_base + (GA_L - GA_H);
    uint32_t b_base  = smb + GB_H + lq*272 + (wl*64 + lh*16);
    uint32_t bl_base = b_base + (GB_L - GB_H);
    for (int kc = 0; kc < K; kc += 64) {
#pragma unroll
        for (int rep = 0; rep < 4; rep++) {
            int idx = tid + rep*256;
            int row = idx >> 3, c4 = idx & 7;
            size_t go = (size_t)(m0 + row)*lda32 + (kc >> 1) + c4*4;
            *(uint4*)(sm + GA_H + row*144 + c4*16) = *(const uint4*)&Ah[go];
            *(uint4*)(sm + GA_L + row*144 + c4*16) = *(const uint4*)&Al[go];
        }
#pragma unroll
        for (int rep = 0; rep < 4; rep++) {
            int idx = tid + rep*256;
            int row = idx >> 4, c4 = idx & 15;
            size_t go = (size_t)(kc + row)*ldb32 + (n0 >> 1) + c4*4;
            *(uint4*)(sm + GB_H + row*272 + c4*16) = *(const uint4*)&Bh[go];
            *(uint4*)(sm + GB_L + row*272 + c4*16) = *(const uint4*)&Bl[go];
        }
        __syncthreads();
#pragma unroll
        for (int kt = 0; kt < 4; kt++) {
            uint32_t a_hi[4][4], a_lo[4][4];
#pragma unroll
            for (int mt = 0; mt < 4; mt++) {
                ldm_x4(a_hi[mt], a_base  + mt*2304 + kt*32);
                ldm_x4(a_lo[mt], al_base + mt*2304 + kt*32);
            }
#pragma unroll
            for (int lt = 0; lt < 2; lt++) {
                uint32_t b_hi[4], b_lo[4];
                ldm_x4_t(b_hi, b_base  + kt*4352 + lt*32);
                ldm_x4_t(b_lo, bl_base + kt*4352 + lt*32);
#pragma unroll
                for (int mt = 0; mt < 4; mt++) {
#pragma unroll
                    for (int f = 0; f < 2; f++) {
                        float* d = acc[mt][lt*2 + f];
                        mma_bf16(d, a_hi[mt], &b_hi[f*2]);
                        mma_bf16(d, a_lo[mt], &b_hi[f*2]);
                        mma_bf16(d, a_hi[mt], &b_lo[f*2]);
                    }
                }
            }
        }
        __syncthreads();
    }
}

// ---------------- K_RS_ENTU: fused rs GEMM (120 blocks) + entU (48 blocks) -----
__global__ __launch_bounds__(256, 2) void k_rs_entU(const float* __restrict__ hW,
                                                    const float* __restrict__ tW) {
    extern __shared__ char sm[];
    int bid = blockIdx.x;
    int tid = threadIdx.x;
    if (bid < 120) {
        int b = bid / 30;
        int rem = bid % 30;
        int m0 = (rem % 5) * 128, n0 = (rem / 5) * 128;
        float acc[4][4][4] = {};
        gemm_main(acc,
                  g_ht_hi + (size_t)b*640*512, g_ht_lo + (size_t)b*640*512,
                  g_seq_hi + (size_t)b*Cc*384, g_seq_lo + (size_t)b*Cc*384,
                  Cc, Dd, m0, n0);
        int lane = tid & 31, wid = tid >> 5;
        int wn = wid >> 2, wl = wid & 3;
        int rbase = m0 + wn*64 + (lane >> 2);
        int cbase = n0 + wl*32 + (lane & 3)*2;
#pragma unroll
        for (int mt = 0; mt < 4; mt++) {
#pragma unroll
            for (int lf = 0; lf < 4; lf++) {
                int r = rbase + mt*16;
                int cp = (cbase + lf*8) >> 1;
                float* d = acc[mt][lf];
                if (r < Pp) {
                    uint32_t h, l;
                    pack2(d[0], d[1], h, l);
                    g_rs_hi[((size_t)(b*Pp + r))*384 + cp] = h;
                    g_rs_lo[((size_t)(b*Pp + r))*384 + cp] = l;
                }
                if (r + 8 < Pp) {
                    uint32_t h, l;
                    pack2(d[2], d[3], h, l);
                    g_rs_hi[((size_t)(b*Pp + r + 8))*384 + cp] = h;
                    g_rs_lo[((size_t)(b*Pp + r + 8))*384 + cp] = l;
                }
            }
        }
    } else {
        // ---- entU: ent_emb @ W_top (SIMT)
        int idx = bid - 120;
        int mb = (idx & 1) * 64;
        int nb = ((idx >> 1) % 12) * 64;
        int s  = idx / 24;
        const float* W = s ? tW : hW;
        float* As = (float*)sm;
        float* Bs = (float*)(sm + 4096);
        int tm = tid >> 4, tn = tid & 15;
        int lm = tid & 63, lk4 = (tid >> 6) << 2;
        float acc[4][4] = {};
        for (int kc = 0; kc < Dd; kc += 16) {
            float4 av = make_float4(0.f,0.f,0.f,0.f);
            int m = mb + lm;
            if (m < Bq*Ee) av = *(const float4*)&g_ent_emb[(size_t)m*Dd + kc + lk4];
            As[(lk4+0)*64+lm] = av.x; As[(lk4+1)*64+lm] = av.y;
            As[(lk4+2)*64+lm] = av.z; As[(lk4+3)*64+lm] = av.w;
#pragma unroll
            for (int r = 0; r < 4; r++) {
                int kk = lk4 + r;
                Bs[kk*64+lm] = W[(size_t)(kc+kk)*EMBn + nb + lm];
            }
            __syncthreads();
#pragma unroll
            for (int kk = 0; kk < 16; kk++) {
                float4 a4 = *(const float4*)&As[kk*64 + tm*4];
                float4 b4 = *(const float4*)&Bs[kk*64 + tn*4];
                acc[0][0] += a4.x*b4.x; acc[0][1] += a4.x*b4.y; acc[0][2] += a4.x*b4.z; acc[0][3] += a4.x*b4.w;
                acc[1][0] += a4.y*b4.x; acc[1][1] += a4.y*b4.y; acc[1][2] += a4.y*b4.z; acc[1][3] += a4.y*b4.w;
                acc[2][0] += a4.z*b4.x; acc[2][1] += a4.z*b4.y; acc[2][2] += a4.z*b4.z; acc[2][3] += a4.z*b4.w;
                acc[3][0] += a4.w*b4.x; acc[3][1] += a4.w*b4.y; acc[3][2] += a4.w*b4.z; acc[3][3] += a4.w*b4.w;
            }
            __syncthreads();
        }
#pragma unroll
        for (int a = 0; a < 4; a++) {
            int m = mb + tm*4 + a;
            if (m < Bq*Ee)
                *(float4*)&g_U[((size_t)s*Bq*Ee + m)*EMBn + nb + tn*4] =
                    make_float4(acc[a][0], acc[a][1], acc[a][2], acc[a][3]);
        }
    }
}

// ---------------- K_RW: rs @ [Wbh|Wbt]; fused U-gather + bias + tanh ------------
__global__ __launch_bounds__(256, 2) void k_rw_mma(const int* __restrict__ hts,
                                                   const float* __restrict__ hb,
                                                   const float* __restrict__ tb) {
    int m0 = blockIdx.x * 128, n0 = blockIdx.y * 128;
    float acc[4][4][4] = {};
    gemm_main(acc, g_rs_hi, g_rs_lo, g_wb_hi, g_wb_lo, Dd, 1536, m0, n0);
    int tid = threadIdx.x, lane = tid & 31, wid = tid >> 5;
    int wn = wid >> 2, wl = wid & 3;
    int rbase = m0 + wn*64 + (lane >> 2);
    int cbase = n0 + wl*32 + (lane & 3)*2;
#pragma unroll
    for (int mt = 0; mt < 4; mt++) {
#pragma unroll
        for (int rr = 0; rr < 2; rr++) {
            int r = rbase + mt*16 + rr*8;
            if (r >= NTOT) continue;
            int b = r / Pp;
            int e0 = hts[r*2 + 0], e1 = hts[r*2 + 1];
#pragma unroll
            for (int lf = 0; lf < 4; lf++) {
                int c = cbase + lf*8;
                int s = (c >= 768);
                int cc = c - (s ? 768 : 0);
                int e = s ? e1 : e0;
                const float* Ur = g_U + ((size_t)(s*Bq*Ee + b*Ee + e))*EMBn + cc;
                const float* bi = (s ? tb : hb) + cc;
                float* dst = (s ? g_tz : g_hz) + (size_t)r*EMBn + cc;
                float* d = acc[mt][lf];
                float2 o;
                o.x = tanhf(d[rr*2 + 0] + Ur[0] + bi[0]);
                o.y = tanhf(d[rr*2 + 1] + Ur[1] + bi[1]);
                *(float2*)dst = o;
            }
        }
    }
}

// ---------------- K_BILIN_C96: fp16x3 bilinear (240 @128-row, occ2) + c96 (228) -
#define SB_AH 0          // A hi: 128 x 144B
#define SB_AL 18432      // A lo
#define SB_B0 36864      // B stages: 2 x (hi 13312 + lo 13312)
#define SB_BUF 26624
#define SB_TOT 90112

__global__ __launch_bounds__(256, 2) void k_bilin_c96() {
    extern __shared__ char sm[];
    uint32_t smb = smem_u32(sm);
    int bid = blockIdx.x;
    int tid = threadIdx.x, lane = tid & 31, wid = tid >> 5;

    if (bid >= 240) {
        // ---- c96: exact fp32 column 96 (128-row tiles)
        int idx = bid - 240;
        int n0 = (idx % 19) * 128, k = idx / 19;
        float* Ws  = (float*)sm;          // [64][64]
        float* hzs = Ws + 4096;           // [128][65]
        float* tzs = hzs + 128*65;        // [128][65]
        for (int e = tid; e < 4096; e += 256)
            Ws[e] = g_w96[(size_t)k*4096 + e];
        for (int e = tid; e < 128*64; e += 256) {
            int r = e >> 6, c = e & 63;
            int n = n0 + r;
            float hv = 0.f, tv = 0.f;
            if (n < NTOT) {
                hv = g_hz[(size_t)n*EMBn + k*64 + c];
                tv = g_tz[(size_t)n*EMBn + k*64 + c];
            }
            hzs[r*65 + c] = hv;
            tzs[r*65 + c] = tv;
        }
        __syncthreads();
        if (tid < 128) {
            float tzr[64];
#pragma unroll
            for (int j = 0; j < 64; j++) tzr[j] = tzs[tid*65 + j];
            float acc = 0.f;
            for (int i = 0; i < 64; i++) {
                const float4* wr = (const float4*)&Ws[i*64];
                float s = 0.f;
#pragma unroll
                for (int j4 = 0; j4 < 16; j4++) {
                    float4 w = wr[j4];
                    s += w.x*tzr[j4*4] + w.y*tzr[j4*4+1] + w.z*tzr[j4*4+2] + w.w*tzr[j4*4+3];
                }
                acc += hzs[tid*65 + i] * s;
            }
            int n = n0 + tid;
            if (n < NTOT) g_part[((size_t)k*NPAD + n)*128 + 96] = acc;
        }
        return;
    }

    // ---- bilinear: 128-row tile, wn4 x wl2
    int n0 = (bid % 20) * 128, k = bid / 20;
    int anl = tid >> 1, ajh = tid & 1;

    float tz[32];
    {
        const float* tzp = g_tz + (size_t)(n0 + anl)*EMBn + k*64 + ajh*32;
#pragma unroll
        for (int j = 0; j < 32; j++) tz[j] = tzp[j];
    }
    const float* hzp = g_hz + (size_t)(n0 + anl)*EMBn + k*64;

    int wn = wid >> 1, wl = wid & 1;
    int lq = lane & 15, lh = lane >> 4;
    uint32_t a_base  = smb + SB_AH + (wn*32 + lq)*144 + lh*16;
    uint32_t al_base = a_base + (SB_AL - SB_AH);
    uint32_t b_off   = lq*208 + wl*96 + lh*16;

    {
        const uint4* srch = ((const uint4*)g_wtf) + (size_t)(k*64)*768;
        const uint4* srcl = ((const uint4*)g_wtl) + (size_t)(k*64)*768;
#pragma unroll
        for (int rep = 0; rep < 3; rep++) {
            int idx = tid + rep*256;
            int j = idx / 12, c = idx % 12;
            CPASYNC(smb + SB_B0 + j*208 + c*16, srch + idx);
            CPASYNC(smb + SB_B0 + 13312 + j*208 + c*16, srcl + idx);
        }
        CPCOMMIT();
    }

    float acc[2][6][4] = {};

    for (int i = 0; i < 64; i++) {
        if (i < 63) {
            size_t blob = (size_t)(k*64 + i + 1) * 768;
            const uint4* srch = ((const uint4*)g_wtf) + blob;
            const uint4* srcl = ((const uint4*)g_wtl) + blob;
            uint32_t dst = smb + SB_B0 + ((i + 1) & 1) * SB_BUF;
#pragma unroll
            for (int rep = 0; rep < 3; rep++) {
                int idx = tid + rep*256;
                int j = idx / 12, c = idx % 12;
                CPASYNC(dst + j*208 + c*16, srch + idx);
                CPASYNC(dst + 13312 + j*208 + c*16, srcl + idx);
            }
            CPCOMMIT();
        }
        float hzv = hzp[i];
        char* ah = sm + SB_AH + anl*144 + ajh*64;
        char* al = sm + SB_AL + anl*144 + ajh*64;
#pragma unroll
        for (int g = 0; g < 4; g++) {
            uint32_t h[4], l[4];
            pack2h(hzv*tz[g*8+0], hzv*tz[g*8+1], h[0], l[0]);
            pack2h(hzv*tz[g*8+2], hzv*tz[g*8+3], h[1], l[1]);
            pack2h(hzv*tz[g*8+4], hzv*tz[g*8+5], h[2], l[2]);
            pack2h(hzv*tz[g*8+6], hzv*tz[g*8+7], h[3], l[3]);
            *(uint4*)(ah + g*16) = make_uint4(h[0], h[1], h[2], h[3]);
            *(uint4*)(al + g*16) = make_uint4(l[0], l[1], l[2], l[3]);
        }
        if (i < 63) { CPWAIT(1); } else { CPWAIT(0); }
        __syncthreads();
        uint32_t bhi = smb + SB_B0 + (i & 1) * SB_BUF;
        uint32_t blo = bhi + 13312;
#pragma unroll
        for (int kt = 0; kt < 4; kt++) {
            uint32_t bh[3][4], bl[3][4];
#pragma unroll
            for (int g = 0; g < 3; g++) {
                ldm_x4_t(bh[g], bhi + b_off + g*32 + kt*3328);
                ldm_x4_t(bl[g], blo + b_off + g*32 + kt*3328);
            }
#pragma unroll
            for (int mt = 0; mt < 2; mt++) {
                uint32_t a_hi[4], a_lo[4];
                ldm_x4(a_hi, a_base  + mt*2304 + kt*32);
                ldm_x4(a_lo, al_base + mt*2304 + kt*32);
#pragma unroll
                for (int lf = 0; lf < 6; lf++) {
                    float* d = acc[mt][lf];
                    int g = lf >> 1, hh = (lf & 1) * 2;
                    mma_f16(d, a_hi, &bh[g][hh]);
                    mma_f16(d, a_lo, &bh[g][hh]);
                    mma_f16(d, a_hi, &bl[g][hh]);
                }
            }
        }
        __syncthreads();
    }
    int rbase = n0 + wn*32 + (lane >> 2);
    int cbase = wl*48 + (lane & 3)*2;
#pragma unroll
    for (int mt = 0; mt < 2; mt++) {
#pragma unroll
        for (int lf = 0; lf < 6; lf++) {
            int r = rbase + mt*16;
            int c = cbase + lf*8;
            float* d = acc[mt][lf];
            *(float2*)&g_part[((size_t)k*NPAD + r)*128 + c]     = make_float2(d[0], d[1]);
            *(float2*)&g_part[((size_t)k*NPAD + r + 8)*128 + c] = make_float2(d[2], d[3]);
        }
    }
}

// ---------------- reduce split partials + bias -> logits -----------------------
__global__ void k_logits(const float* __restrict__ bb, float* __restrict__ out) {
    int g = blockIdx.x * 256 + threadIdx.x;
    if (g >= NTOT*NL) return;
    int n = g / NL, l = g % NL;
    float s = bb[l];
#pragma unroll
    for (int sp = 0; sp < NSPLIT; sp++)
        s += g_part[((size_t)sp*NPAD + n)*128 + l];
    out[1 + (size_t)n*NL + l] = s;
}

// ---------------- K_RISK_ALL: per-class risk + last-block total -----------------
__global__ void k_risk_all(const float* __restrict__ out_ro, const int* __restrict__ labels,
                           const float* __restrict__ pl, const float* __restrict__ po,
                           float* __restrict__ out) {
    int r = blockIdx.x;
    int tid = threadIdx.x;
    float s_neg = 0.f, s_pp = 0.f, s_pn = 0.f, c_pos = 0.f;
    for (int n = tid; n < NTOT; n += 256) {
        float l0 = out_ro[1 + (size_t)n*NL];
        float sc = out_ro[1 + (size_t)n*NL + (r+1)] - l0;
        bool pos = labels[(size_t)n*NL + (r+1)] == 1;
        float lp = 0.25f * (sc - 1.f) * (sc - 1.f);
        float ln = 0.25f * (-sc - 1.f) * (-sc - 1.f);
        if (pos) { c_pos += 1.f; s_pp += lp; s_pn += ln; }
        else     { s_neg += ln; }
    }
    __shared__ float red[4][256];
    red[0][tid] = s_neg; red[1][tid] = s_pp; red[2][tid] = s_pn; red[3][tid] = c_pos;
    __syncthreads();
    for (int st = 128; st > 0; st >>= 1) {
        if (tid < st) {
#pragma unroll
            for (int q = 0; q < 4; q++) red[q][tid] += red[q][tid + st];
        }
        __syncthreads();
    }
    __shared__ unsigned int s_last;
    if (tid == 0) {
        float cp = red[3][0], cn = (float)NTOT - cp;
        float sq_neg = (cn > 0.f) ? red[0][0] / fmaxf(cn, 1.f) : 0.f;
        float sq_pp  = (cp > 0.f) ? red[1][0] / fmaxf(cp, 1.f) : 0.f;
        float sq_pn  = (cp > 0.f) ? red[2][0] / fmaxf(cp, 1.f) : 0.f;
        float o = po[r], lq = pl[r];
        float w  = sqrtf((1.f - o) / o);
        float pu = (o - lq) / (1.f - lq);
        float risk1 = (1.f - o)/(1.f - pu)*sq_neg - (pu - pu*o)/(1.f - pu)*sq_pn;
        float risk2 = o * sq_pp * w;
        g_riskc[r] = (risk1 < 0.f) ? -risk1 : (risk1 + risk2);
        __threadfence();
        s_last = atomicAdd(&g_rdone, 1u);
    }
    __syncthreads();
    if (s_last == RELSn - 1) {
        __threadfence();
        __shared__ float rr[128];
        if (tid < 128) rr[tid] = (tid < RELSn) ? g_riskc[tid] : 0.f;
        __syncthreads();
        for (int st = 64; st > 0; st >>= 1) {
            if (tid < st) rr[tid] += rr[tid + st];
            __syncthreads();
        }
        if (tid == 0) { out[0] = rr[0]; g_rdone = 0; }
    }
}

// ---------------- launch ---------------------------------------------------------
extern "C" void kernel_launch(void* const* d_in, const int* in_sizes, int n_in,
                              void* d_out, int out_size) {
    const float* seq      = (const float*)d_in[0];
    const float* att      = (const float*)d_in[1];
    const int*   midx     = (const int*)  d_in[2];
    const float* mmask    = (const float*)d_in[3];
    const int*   hts      = (const int*)  d_in[4];
    const int*   labels   = (const int*)  d_in[5];
    const float* priors_l = (const float*)d_in[6];
    const float* priors_o = (const float*)d_in[7];
    const float* head_W   = (const float*)d_in[8];
    const float* head_b   = (const float*)d_in[9];
    const float* tail_W   = (const float*)d_in[10];
    const float* tail_b   = (const float*)d_in[11];
    const float* bil_W    = (const float*)d_in[12];
    const float* bil_b    = (const float*)d_in[13];
    float* out = (float*)d_out;

    cudaFuncSetAttribute(k_bilin_c96, cudaFuncAttributeMaxDynamicSharedMemorySize, SB_TOT);
    cudaFuncSetAttribute(k_rs_entU,   cudaFuncAttributeMaxDynamicSharedMemorySize, GEMM_SM);
    cudaFuncSetAttribute(k_rw_mma,    cudaFuncAttributeMaxDynamicSharedMemorySize, GEMM_SM);

    k_prep<<<3384, 256>>>(seq, att, midx, mmask, bil_W, head_W, tail_W);
    k_ht<<<NTOT, 256>>>(hts);
    k_rs_entU<<<168, 256, GEMM_SM>>>(head_W, tail_W);
    k_rw_mma<<<dim3(19, 12), 256, GEMM_SM>>>(hts, head_b, tail_b);
    k_bilin_c96<<<468, 256, SB_TOT>>>();
    k_logits<<<(NTOT*NL + 255)/256, 256>>>(bil_b, out);
    k_risk_all<<<RELSn, 256>>>(out, labels, priors_l, priors_o, out);
}

// round 15
// speedup vs baseline: 1.5430x; 1.0360x over previous
#include <cuda_runtime.h>
#include <cuda_bf16.h>
#include <cuda_fp16.h>
#include <math.h>
#include <stdint.h>

#define Bq    4
#define Hh    12
#define Cc    1024
#define Dd    768
#define Ee    30
#define Mm    8
#define Pp    600
#define NL    97
#define RELSn 96
#define EMBn  768
#define NTOT  2400   // B*P
#define NPAD  2560   // pad rows stay zero
#define NSPLIT 12    // k blocks

// ---------------- scratch (static device globals; no allocation) -------------
__device__ float g_ent_emb[Bq*Ee*Dd];          // [B,E,D]
__device__ float g_ent_att[Bq*Ee*Hh*Cc];       // [B,E,H,C]
__device__ float g_hz[NPAD*EMBn];              // rows >=2400 stay zero
__device__ float g_tz[NPAD*EMBn];
__device__ uint32_t g_wtf[768*3072];           // bil W fp16 hi: [blob][64 j][48 lpair]
__device__ uint32_t g_wtl[768*3072];           // bil W fp16 lo (residual)
__device__ float    g_w96[768*64];             // bil W col 96: [blob][j]
__device__ uint32_t g_ht_hi[Bq*640*512];       // ht_att bf16 pairs [b][640][512]
__device__ uint32_t g_ht_lo[Bq*640*512];
__device__ uint32_t g_seq_hi[Bq*Cc*384];       // seq bf16 pairs [b][1024][384]
__device__ uint32_t g_seq_lo[Bq*Cc*384];
__device__ uint32_t g_rs_hi[2432*384];         // rs bf16 pairs (pad rows zero)
__device__ uint32_t g_rs_lo[2432*384];
__device__ uint32_t g_wb_hi[768*768];          // [W_bot_head | W_bot_tail] pairs
__device__ uint32_t g_wb_lo[768*768];
__device__ float g_U[2*Bq*Ee*EMBn];            // ent_emb @ W_top (head, tail)
__device__ float g_part[NSPLIT*NPAD*128];      // split partial logits
__device__ float g_riskc[RELSn];
__device__ unsigned int g_rdone = 0;

// =================== helpers ===================================================
__device__ __forceinline__ uint32_t smem_u32(const void* p) {
    uint32_t a;
    asm("{ .reg .u64 t; cvta.to.shared.u64 t, %1; cvt.u32.u64 %0, t; }" : "=r"(a) : "l"(p));
    return a;
}
__device__ __forceinline__ void pack2(float p0, float p1, uint32_t& hi, uint32_t& lo) {
    uint32_t h;
    asm("cvt.rn.bf16x2.f32 %0, %1, %2;" : "=r"(h) : "f"(p1), "f"(p0));
    float h0 = __uint_as_float(h << 16);
    float h1 = __uint_as_float(h & 0xFFFF0000u);
    float l0 = p0 - h0, l1 = p1 - h1;
    uint32_t l;
    asm("cvt.rn.bf16x2.f32 %0, %1, %2;" : "=r"(l) : "f"(l1), "f"(l0));
    hi = h; lo = l;
}
__device__ __forceinline__ void pack2h(float p0, float p1, uint32_t& hi, uint32_t& lo) {
    __half2 h = __floats2half2_rn(p0, p1);
    float2 hf = __half22float2(h);
    __half2 l = __floats2half2_rn(p0 - hf.x, p1 - hf.y);
    hi = *(uint32_t*)&h;
    lo = *(uint32_t*)&l;
}
__device__ __forceinline__ void ldm_x4(uint32_t* r, uint32_t addr) {
    asm volatile("ldmatrix.sync.aligned.m8n8.x4.shared.b16 {%0,%1,%2,%3}, [%4];"
        : "=r"(r[0]), "=r"(r[1]), "=r"(r[2]), "=r"(r[3]) : "r"(addr));
}
__device__ __forceinline__ void ldm_x4_t(uint32_t* r, uint32_t addr) {
    asm volatile("ldmatrix.sync.aligned.m8n8.x4.trans.shared.b16 {%0,%1,%2,%3}, [%4];"
        : "=r"(r[0]), "=r"(r[1]), "=r"(r[2]), "=r"(r[3]) : "r"(addr));
}
__device__ __forceinline__ void mma_bf16(float* d, const uint32_t* a, const uint32_t* b) {
    asm volatile(
        "mma.sync.aligned.m16n8k16.row.col.f32.bf16.bf16.f32 "
        "{%0,%1,%2,%3}, {%4,%5,%6,%7}, {%8,%9}, {%0,%1,%2,%3};"
        : "+f"(d[0]), "+f"(d[1]), "+f"(d[2]), "+f"(d[3])
        : "r"(a[0]), "r"(a[1]), "r"(a[2]), "r"(a[3]), "r"(b[0]), "r"(b[1]));
}
__device__ __forceinline__ void mma_f16(float* d, const uint32_t* a, const uint32_t* b) {
    asm volatile(
        "mma.sync.aligned.m16n8k16.row.col.f32.f16.f16.f32 "
        "{%0,%1,%2,%3}, {%4,%5,%6,%7}, {%8,%9}, {%0,%1,%2,%3};"
        : "+f"(d[0]), "+f"(d[1]), "+f"(d[2]), "+f"(d[3])
        : "r"(a[0]), "r"(a[1]), "r"(a[2]), "r"(a[3]), "r"(b[0]), "r"(b[1]));
}
#define CPASYNC(dst, src) asm volatile("cp.async.cg.shared.global [%0], [%1], 16;" :: "r"(dst), "l"(src))
#define CPCOMMIT()        asm volatile("cp.async.commit_group;")
#define CPWAIT(n)         asm volatile("cp.async.wait_group %0;" :: "n"(n) : "memory")

// ---------------- K_PREP: fused ent_att | wsplit | ent_emb | wbsplit | seqsplit -
__global__ __launch_bounds__(256) void k_prep(
    const float* __restrict__ seq, const float* __restrict__ att,
    const int* __restrict__ midx, const float* __restrict__ mmask,
    const float* __restrict__ bilW,
    const float* __restrict__ hW, const float* __restrict__ tW)
{
    int bid = blockIdx.x;
    int tid = threadIdx.x;
    __shared__ int   s_idx[Mm];
    __shared__ float s_w[Mm];

    if (bid < 1440) {
        int g  = bid;
        int h  = g % Hh;
        int be = g / Hh;
        int b  = be / Ee;
        if (tid < Mm) {
            s_idx[tid] = midx[be*Mm + tid] + 1;
            s_w[tid]   = mmask[be*Mm + tid];
        }
        __syncthreads();
        float cnt = 0.f;
#pragma unroll
        for (int m = 0; m < Mm; m++) cnt += s_w[m];
        float inv = 1.f / cnt;
        const float* base = att + ((size_t)b*Hh + h)*Cc*Cc;
        for (int c = tid; c < Cc; c += 256) {
            float s = 0.f;
#pragma unroll
            for (int m = 0; m < Mm; m++)
                s += s_w[m] * base[(size_t)s_idx[m]*Cc + c];
            g_ent_att[(size_t)g*Cc + c] = s * inv;
        }
    } else if (bid < 2208) {
        int blob = bid - 1440;
        int j = tid >> 2, lq = (tid & 3) * 24;
        size_t row = ((size_t)blob*64 + j) * NL;
        uint32_t* oh = g_wtf + ((size_t)blob*64 + j)*48 + (lq >> 1);
        uint32_t* ol = g_wtl + ((size_t)blob*64 + j)*48 + (lq >> 1);
#pragma unroll
        for (int q = 0; q < 12; q++) {
            int l0 = lq + q*2;
            float v0 = bilW[row + l0];
            float v1 = bilW[row + l0 + 1];
            uint32_t h, l;
            pack2h(v0, v1, h, l);
            oh[q] = h; ol[q] = l;
        }
        if ((tid & 3) == 0) g_w96[(size_t)blob*64 + j] = bilW[row + 96];
    } else if (bid < 2328) {
        int be = bid - 2208;
        int b  = be / Ee;
        if (tid < Mm) {
            s_idx[tid] = midx[be*Mm + tid] + 1;
            s_w[tid]   = mmask[be*Mm + tid];
        }
        __syncthreads();
        for (int d = tid; d < Dd; d += 256) {
            float xv[Mm];
            float mx = -1e30f;
#pragma unroll
            for (int m = 0; m < Mm; m++) {
                float x = seq[((size_t)b*Cc + s_idx[m])*Dd + d];
                xv[m] = x;
                if (s_w[m] > 0.f) mx = fmaxf(mx, x);
            }
            float s = 0.f;
#pragma unroll
            for (int m = 0; m < Mm; m++)
                if (s_w[m] > 0.f) s += s_w[m] * __expf(xv[m] - mx);
            g_ent_emb[(size_t)be*Dd + d] = __logf(s) + mx;
        }
    } else if (bid < 2904) {
        int i0 = (bid - 2328)*1024 + tid*4;
#pragma unroll
        for (int q = 0; q < 4; q++) {
            int i = i0 + q;
            int kk = i / 768, c = i % 768;
            int c2 = c*2;
            const float* W = (c2 < 768) ? hW : tW;
            int col = (c2 < 768) ? c2 : (c2 - 768);
            size_t ro = (size_t)(768 + kk) * EMBn;
            uint32_t h, l;
            pack2(W[ro + col], W[ro + col + 1], h, l);
            g_wb_hi[i] = h; g_wb_lo[i] = l;
        }
    } else {
        int i0 = (bid - 2904)*1024 + tid*4;
#pragma unroll
        for (int q = 0; q < 4; q++) {
            int i = i0 + q;
            uint32_t h, l;
            pack2(seq[(size_t)i*2], seq[(size_t)i*2+1], h, l);
            g_seq_hi[i] = h; g_seq_lo[i] = l;
        }
    }
}

// ---------------- K_HT: ht_att -> bf16 hi/lo split ------------------------------
__global__ void k_ht(const int* __restrict__ hts) {
    int n = blockIdx.x;
    int b = n / Pp, p = n % Pp;
    int hi = hts[n*2 + 0], ti = hts[n*2 + 1];
    size_t hb = (size_t)(b*Ee + hi) * Hh * Cc;
    size_t tb = (size_t)(b*Ee + ti) * Hh * Cc;
    __shared__ float vals[Cc];
    __shared__ float red[256];
    float loc = 0.f;
    for (int c = threadIdx.x; c < Cc; c += 256) {
        float s = 0.f;
#pragma unroll
        for (int h = 0; h < Hh; h++)
            s += g_ent_att[hb + (size_t)h*Cc + c] * g_ent_att[tb + (size_t)h*Cc + c];
        s *= (1.f / Hh);
        vals[c] = s;
        loc += s;
    }
    red[threadIdx.x] = loc;
    __syncthreads();
    for (int st = 128; st > 0; st >>= 1) {
        if (threadIdx.x < st) red[threadIdx.x] += red[threadIdx.x + st];
        __syncthreads();
    }
    float invt = 1.f / (red[0] + 1e-5f);
    uint32_t* oh = g_ht_hi + ((size_t)b*640 + p)*512;
    uint32_t* ol = g_ht_lo + ((size_t)b*640 + p)*512;
    for (int c2 = threadIdx.x; c2 < 512; c2 += 256) {
        float v0 = vals[c2*2]   * invt;
        float v1 = vals[c2*2+1] * invt;
        uint32_t h, l;
        pack2(v0, v1, h, l);
        oh[c2] = h; ol[c2] = l;
    }
}

// ---------------- bf16x3 mma GEMM mainloop (128x128 tile, 256 thr, occ2) -------
#define GA_H 0
#define GA_L 18432
#define GB_H 36864
#define GB_L 54272
#define GEMM_SM 71680

__device__ __forceinline__ void gemm_main(float acc[4][4][4],
    const uint32_t* __restrict__ Ah, const uint32_t* __restrict__ Al,
    const uint32_t* __restrict__ Bh, const uint32_t* __restrict__ Bl,
    int K, int N, int m0, int n0)
{
    extern __shared__ char sm[];
    uint32_t smb = smem_u32(sm);
    int tid = threadIdx.x, lane = tid & 31, wid = tid >> 5;
    int lda32 = K >> 1, ldb32 = N >> 1;
    int wn = wid >> 2, wl = wid & 3, lq = lane & 15, lh = lane >> 4;
    uint32_t a_base  = smb + GA_H + (wn*64 + lq)*144 + lh*16;
    uint32_t al_base = a_base + (GA_L - GA_H);
    uint32_t b_base  = smb + GB_H + lq*272 + (wl*64 + lh*16);
    uint32_t bl_base = b_base + (GB_L - GB_H);
    for (int kc = 0; kc < K; kc += 64) {
#pragma unroll
        for (int rep = 0; rep < 4; rep++) {
            int idx = tid + rep*256;
            int row = idx >> 3, c4 = idx & 7;
            size_t go = (size_t)(m0 + row)*lda32 + (kc >> 1) + c4*4;
            *(uint4*)(sm + GA_H + row*144 + c4*16) = *(const uint4*)&Ah[go];
            *(uint4*)(sm + GA_L + row*144 + c4*16) = *(const uint4*)&Al[go];
        }
#pragma unroll
        for (int rep = 0; rep < 4; rep++) {
            int idx = tid + rep*256;
            int row = idx >> 4, c4 = idx & 15;
            size_t go = (size_t)(kc + row)*ldb32 + (n0 >> 1) + c4*4;
            *(uint4*)(sm + GB_H + row*272 + c4*16) = *(const uint4*)&Bh[go];
            *(uint4*)(sm + GB_L + row*272 + c4*16) = *(const uint4*)&Bl[go];
        }
        __syncthreads();
#pragma unroll
        for (int kt = 0; kt < 4; kt++) {
            uint32_t a_hi[4][4], a_lo[4][4];
#pragma unroll
            for (int mt = 0; mt < 4; mt++) {
                ldm_x4(a_hi[mt], a_base  + mt*2304 + kt*32);
                ldm_x4(a_lo[mt], al_base + mt*2304 + kt*32);
            }
#pragma unroll
            for (int lt = 0; lt < 2; lt++) {
                uint32_t b_hi[4], b_lo[4];
                ldm_x4_t(b_hi, b_base  + kt*4352 + lt*32);
                ldm_x4_t(b_lo, bl_base + kt*4352 + lt*32);
#pragma unroll
                for (int mt = 0; mt < 4; mt++) {
#pragma unroll
                    for (int f = 0; f < 2; f++) {
                        float* d = acc[mt][lt*2 + f];
                        mma_bf16(d, a_hi[mt], &b_hi[f*2]);
                        mma_bf16(d, a_lo[mt], &b_hi[f*2]);
                        mma_bf16(d, a_hi[mt], &b_lo[f*2]);
                    }
                }
            }
        }
        __syncthreads();
    }
}

// ---------------- K_RS_ENTU: fused rs GEMM (120 blocks) + entU (48 blocks) -----
__global__ __launch_bounds__(256, 2) void k_rs_entU(const float* __restrict__ hW,
                                                    const float* __restrict__ tW) {
    extern __shared__ char sm[];
    int bid = blockIdx.x;
    int tid = threadIdx.x;
    if (bid < 120) {
        int b = bid / 30;
        int rem = bid % 30;
        int m0 = (rem % 5) * 128, n0 = (rem / 5) * 128;
        float acc[4][4][4] = {};
        gemm_main(acc,
                  g_ht_hi + (size_t)b*640*512, g_ht_lo + (size_t)b*640*512,
                  g_seq_hi + (size_t)b*Cc*384, g_seq_lo + (size_t)b*Cc*384,
                  Cc, Dd, m0, n0);
        int lane = tid & 31, wid = tid >> 5;
        int wn = wid >> 2, wl = wid & 3;
        int rbase = m0 + wn*64 + (lane >> 2);
        int cbase = n0 + wl*32 + (lane & 3)*2;
#pragma unroll
        for (int mt = 0; mt < 4; mt++) {
#pragma unroll
            for (int lf = 0; lf < 4; lf++) {
                int r = rbase + mt*16;
                int cp = (cbase + lf*8) >> 1;
                float* d = acc[mt][lf];
                if (r < Pp) {
                    uint32_t h, l;
                    pack2(d[0], d[1], h, l);
                    g_rs_hi[((size_t)(b*Pp + r))*384 + cp] = h;
                    g_rs_lo[((size_t)(b*Pp + r))*384 + cp] = l;
                }
                if (r + 8 < Pp) {
                    uint32_t h, l;
                    pack2(d[2], d[3], h, l);
                    g_rs_hi[((size_t)(b*Pp + r + 8))*384 + cp] = h;
                    g_rs_lo[((size_t)(b*Pp + r + 8))*384 + cp] = l;
                }
            }
        }
    } else {
        // ---- entU: ent_emb @ W_top (SIMT)
        int idx = bid - 120;
        int mb = (idx & 1) * 64;
        int nb = ((idx >> 1) % 12) * 64;
        int s  = idx / 24;
        const float* W = s ? tW : hW;
        float* As = (float*)sm;
        float* Bs = (float*)(sm + 4096);
        int tm = tid >> 4, tn = tid & 15;
        int lm = tid & 63, lk4 = (tid >> 6) << 2;
        float acc[4][4] = {};
        for (int kc = 0; kc < Dd; kc += 16) {
            float4 av = make_float4(0.f,0.f,0.f,0.f);
            int m = mb + lm;
            if (m < Bq*Ee) av = *(const float4*)&g_ent_emb[(size_t)m*Dd + kc + lk4];
            As[(lk4+0)*64+lm] = av.x; As[(lk4+1)*64+lm] = av.y;
            As[(lk4+2)*64+lm] = av.z; As[(lk4+3)*64+lm] = av.w;
#pragma unroll
            for (int r = 0; r < 4; r++) {
                int kk = lk4 + r;
                Bs[kk*64+lm] = W[(size_t)(kc+kk)*EMBn + nb + lm];
            }
            __syncthreads();
#pragma unroll
            for (int kk = 0; kk < 16; kk++) {
                float4 a4 = *(const float4*)&As[kk*64 + tm*4];
                float4 b4 = *(const float4*)&Bs[kk*64 + tn*4];
                acc[0][0] += a4.x*b4.x; acc[0][1] += a4.x*b4.y; acc[0][2] += a4.x*b4.z; acc[0][3] += a4.x*b4.w;
                acc[1][0] += a4.y*b4.x; acc[1][1] += a4.y*b4.y; acc[1][2] += a4.y*b4.z; acc[1][3] += a4.y*b4.w;
                acc[2][0] += a4.z*b4.x; acc[2][1] += a4.z*b4.y; acc[2][2] += a4.z*b4.z; acc[2][3] += a4.z*b4.w;
                acc[3][0] += a4.w*b4.x; acc[3][1] += a4.w*b4.y; acc[3][2] += a4.w*b4.z; acc[3][3] += a4.w*b4.w;
            }
            __syncthreads();
        }
#pragma unroll
        for (int a = 0; a < 4; a++) {
            int m = mb + tm*4 + a;
            if (m < Bq*Ee)
                *(float4*)&g_U[((size_t)s*Bq*Ee + m)*EMBn + nb + tn*4] =
                    make_float4(acc[a][0], acc[a][1], acc[a][2], acc[a][3]);
        }
    }
}

// ---------------- K_RW: rs @ [Wbh|Wbt]; fused U-gather + bias + tanh ------------
__global__ __launch_bounds__(256, 2) void k_rw_mma(const int* __restrict__ hts,
                                                   const float* __restrict__ hb,
                                                   const float* __restrict__ tb) {
    int m0 = blockIdx.x * 128, n0 = blockIdx.y * 128;
    float acc[4][4][4] = {};
    gemm_main(acc, g_rs_hi, g_rs_lo, g_wb_hi, g_wb_lo, Dd, 1536, m0, n0);
    int tid = threadIdx.x, lane = tid & 31, wid = tid >> 5;
    int wn = wid >> 2, wl = wid & 3;
    int rbase = m0 + wn*64 + (lane >> 2);
    int cbase = n0 + wl*32 + (lane & 3)*2;
#pragma unroll
    for (int mt = 0; mt < 4; mt++) {
#pragma unroll
        for (int rr = 0; rr < 2; rr++) {
            int r = rbase + mt*16 + rr*8;
            if (r >= NTOT) continue;
            int b = r / Pp;
            int e0 = hts[r*2 + 0], e1 = hts[r*2 + 1];
#pragma unroll
            for (int lf = 0; lf < 4; lf++) {
                int c = cbase + lf*8;
                int s = (c >= 768);
                int cc = c - (s ? 768 : 0);
                int e = s ? e1 : e0;
                const float* Ur = g_U + ((size_t)(s*Bq*Ee + b*Ee + e))*EMBn + cc;
                const float* bi = (s ? tb : hb) + cc;
                float* dst = (s ? g_tz : g_hz) + (size_t)r*EMBn + cc;
                float* d = acc[mt][lf];
                float2 o;
                o.x = tanhf(d[rr*2 + 0] + Ur[0] + bi[0]);
                o.y = tanhf(d[rr*2 + 1] + Ur[1] + bi[1]);
                *(float2*)dst = o;
            }
        }
    }
}

// ---------------- K_BILIN_C96: fp16x3 bilinear (240 @128-row, occ2) + c96 (228) -
#define SB_AH 0          // A hi: 128 x 144B
#define SB_AL 18432      // A lo
#define SB_B0 36864      // B stages: 2 x (hi 13312 + lo 13312)
#define SB_BUF 26624
#define SB_TOT 90112

__global__ __launch_bounds__(256, 2) void k_bilin_c96() {
    extern __shared__ char sm[];
    uint32_t smb = smem_u32(sm);
    int bid = blockIdx.x;
    int tid = threadIdx.x, lane = tid & 31, wid = tid >> 5;

    if (bid >= 240) {
        // ---- c96: exact fp32 column 96 (128-row tiles)
        int idx = bid - 240;
        int n0 = (idx % 19) * 128, k = idx / 19;
        float* Ws  = (float*)sm;          // [64][64]
        float* hzs = Ws + 4096;           // [128][65]
        float* tzs = hzs + 128*65;        // [128][65]
        for (int e = tid; e < 4096; e += 256)
            Ws[e] = g_w96[(size_t)k*4096 + e];
        for (int e = tid; e < 128*64; e += 256) {
            int r = e >> 6, c = e & 63;
            int n = n0 + r;
            float hv = 0.f, tv = 0.f;
            if (n < NTOT) {
                hv = g_hz[(size_t)n*EMBn + k*64 + c];
                tv = g_tz[(size_t)n*EMBn + k*64 + c];
            }
            hzs[r*65 + c] = hv;
            tzs[r*65 + c] = tv;
        }
        __syncthreads();
        if (tid < 128) {
            float tzr[64];
#pragma unroll
            for (int j = 0; j < 64; j++) tzr[j] = tzs[tid*65 + j];
            float acc = 0.f;
            for (int i = 0; i < 64; i++) {
                const float4* wr = (const float4*)&Ws[i*64];
                float s = 0.f;
#pragma unroll
                for (int j4 = 0; j4 < 16; j4++) {
                    float4 w = wr[j4];
                    s += w.x*tzr[j4*4] + w.y*tzr[j4*4+1] + w.z*tzr[j4*4+2] + w.w*tzr[j4*4+3];
                }
                acc += hzs[tid*65 + i] * s;
            }
            int n = n0 + tid;
            if (n < NTOT) g_part[((size_t)k*NPAD + n)*128 + 96] = acc;
        }
        return;
    }

    // ---- bilinear: 128-row tile, wn4 x wl2
    int n0 = (bid % 20) * 128, k = bid / 20;
    int anl = tid >> 1, ajh = tid & 1;

    float tz[32];
    {
        const float* tzp = g_tz + (size_t)(n0 + anl)*EMBn + k*64 + ajh*32;
#pragma unroll
        for (int j = 0; j < 32; j++) tz[j] = tzp[j];
    }
    const float* hzp = g_hz + (size_t)(n0 + anl)*EMBn + k*64;

    int wn = wid >> 1, wl = wid & 1;
    int lq = lane & 15, lh = lane >> 4;
    uint32_t a_base  = smb + SB_AH + (wn*32 + lq)*144 + lh*16;
    uint32_t al_base = a_base + (SB_AL - SB_AH);
    uint32_t b_off   = lq*208 + wl*96 + lh*16;

    {
        const uint4* srch = ((const uint4*)g_wtf) + (size_t)(k*64)*768;
        const uint4* srcl = ((const uint4*)g_wtl) + (size_t)(k*64)*768;
#pragma unroll
        for (int rep = 0; rep < 3; rep++) {
            int idx = tid + rep*256;
            int j = idx / 12, c = idx % 12;
            CPASYNC(smb + SB_B0 + j*208 + c*16, srch + idx);
            CPASYNC(smb + SB_B0 + 13312 + j*208 + c*16, srcl + idx);
        }
        CPCOMMIT();
    }

    float acc[2][6][4] = {};

    for (int i = 0; i < 64; i++) {
        if (i < 63) {
            size_t blob = (size_t)(k*64 + i + 1) * 768;
            const uint4* srch = ((const uint4*)g_wtf) + blob;
            const uint4* srcl = ((const uint4*)g_wtl) + blob;
            uint32_t dst = smb + SB_B0 + ((i + 1) & 1) * SB_BUF;
#pragma unroll
            for (int rep = 0; rep < 3; rep++) {
                int idx = tid + rep*256;
                int j = idx / 12, c = idx % 12;
                CPASYNC(dst + j*208 + c*16, srch + idx);
                CPASYNC(dst + 13312 + j*208 + c*16, srcl + idx);
            }
            CPCOMMIT();
        }
        float hzv = hzp[i];
        char* ah = sm + SB_AH + anl*144 + ajh*64;
        char* al = sm + SB_AL + anl*144 + ajh*64;
#pragma unroll
        for (int g = 0; g < 4; g++) {
            uint32_t h[4], l[4];
            pack2h(hzv*tz[g*8+0], hzv*tz[g*8+1], h[0], l[0]);
            pack2h(hzv*tz[g*8+2], hzv*tz[g*8+3], h[1], l[1]);
            pack2h(hzv*tz[g*8+4], hzv*tz[g*8+5], h[2], l[2]);
            pack2h(hzv*tz[g*8+6], hzv*tz[g*8+7], h[3], l[3]);
            *(uint4*)(ah + g*16) = make_uint4(h[0], h[1], h[2], h[3]);
            *(uint4*)(al + g*16) = make_uint4(l[0], l[1], l[2], l[3]);
        }
        if (i < 63) { CPWAIT(1); } else { CPWAIT(0); }
        __syncthreads();
        uint32_t bhi = smb + SB_B0 + (i & 1) * SB_BUF;
        uint32_t blo = bhi + 13312;
#pragma unroll
        for (int kt = 0; kt < 4; kt++) {
            uint32_t bh[3][4], bl[3][4];
#pragma unroll
            for (int g = 0; g < 3; g++) {
                ldm_x4_t(bh[g], bhi + b_off + g*32 + kt*3328);
                ldm_x4_t(bl[g], blo + b_off + g*32 + kt*3328);
            }
#pragma unroll
            for (int mt = 0; mt < 2; mt++) {
                uint32_t a_hi[4], a_lo[4];
                ldm_x4(a_hi, a_base  + mt*2304 + kt*32);
                ldm_x4(a_lo, al_base + mt*2304 + kt*32);
#pragma unroll
                for (int lf = 0; lf < 6; lf++) {
                    float* d = acc[mt][lf];
                    int g = lf >> 1, hh = (lf & 1) * 2;
                    mma_f16(d, a_hi, &bh[g][hh]);
                    mma_f16(d, a_lo, &bh[g][hh]);
                    mma_f16(d, a_hi, &bl[g][hh]);
                }
            }
        }
        __syncthreads();
    }
    int rbase = n0 + wn*32 + (lane >> 2);
    int cbase = wl*48 + (lane & 3)*2;
#pragma unroll
    for (int mt = 0; mt < 2; mt++) {
#pragma unroll
        for (int lf = 0; lf < 6; lf++) {
            int r = rbase + mt*16;
            int c = cbase + lf*8;
            float* d = acc[mt][lf];
            *(float2*)&g_part[((size_t)k*NPAD + r)*128 + c]     = make_float2(d[0], d[1]);
            *(float2*)&g_part[((size_t)k*NPAD + r + 8)*128 + c] = make_float2(d[2], d[3]);
        }
    }
}

// ---------------- reduce split partials + bias -> logits -----------------------
__global__ void k_logits(const float* __restrict__ bb, float* __restrict__ out) {
    int g = blockIdx.x * 256 + threadIdx.x;
    if (g >= NTOT*NL) return;
    int n = g / NL, l = g % NL;
    float s = bb[l];
#pragma unroll
    for (int sp = 0; sp < NSPLIT; sp++)
        s += g_part[((size_t)sp*NPAD + n)*128 + l];
    out[1 + (size_t)n*NL + l] = s;
}

// ---------------- K_RISK_ALL: per-class risk + last-block total -----------------
__global__ void k_risk_all(const float* __restrict__ out_ro, const int* __restrict__ labels,
                           const float* __restrict__ pl, const float* __restrict__ po,
                           float* __restrict__ out) {
    int r = blockIdx.x;
    int tid = threadIdx.x;
    float s_neg = 0.f, s_pp = 0.f, s_pn = 0.f, c_pos = 0.f;
    for (int n = tid; n < NTOT; n += 256) {
        float l0 = out_ro[1 + (size_t)n*NL];
        float sc = out_ro[1 + (size_t)n*NL + (r+1)] - l0;
        bool pos = labels[(size_t)n*NL + (r+1)] == 1;
        float lp = 0.25f * (sc - 1.f) * (sc - 1.f);
        float ln = 0.25f * (-sc - 1.f) * (-sc - 1.f);
        if (pos) { c_pos += 1.f; s_pp += lp; s_pn += ln; }
        else     { s_neg += ln; }
    }
    __shared__ float red[4][256];
    red[0][tid] = s_neg; red[1][tid] = s_pp; red[2][tid] = s_pn; red[3][tid] = c_pos;
    __syncthreads();
    for (int st = 128; st > 0; st >>= 1) {
        if (tid < st) {
#pragma unroll
            for (int q = 0; q < 4; q++) red[q][tid] += red[q][tid + st];
        }
        __syncthreads();
    }
    __shared__ unsigned int s_last;
    if (tid == 0) {
        float cp = red[3][0], cn = (float)NTOT - cp;
        float sq_neg = (cn > 0.f) ? red[0][0] / fmaxf(cn, 1.f) : 0.f;
        float sq_pp  = (cp > 0.f) ? red[1][0] / fmaxf(cp, 1.f) : 0.f;
        float sq_pn  = (cp > 0.f) ? red[2][0] / fmaxf(cp, 1.f) : 0.f;
        float o = po[r], lq = pl[r];
        float w  = sqrtf((1.f - o) / o);
        float pu = (o - lq) / (1.f - lq);
        float risk1 = (1.f - o)/(1.f - pu)*sq_neg - (pu - pu*o)/(1.f - pu)*sq_pn;
        float risk2 = o * sq_pp * w;
        g_riskc[r] = (risk1 < 0.f) ? -risk1 : (risk1 + risk2);
        __threadfence();
        s_last = atomicAdd(&g_rdone, 1u);
    }
    __syncthreads();
    if (s_last == RELSn - 1) {
        __threadfence();
        __shared__ float rr[128];
        if (tid < 128) rr[tid] = (tid < RELSn) ? g_riskc[tid] : 0.f;
        __syncthreads();
        for (int st = 64; st > 0; st >>= 1) {
            if (tid < st) rr[tid] += rr[tid + st];
            __syncthreads();
        }
        if (tid == 0) { out[0] = rr[0]; g_rdone = 0; }
    }
}

// ---------------- launch ---------------------------------------------------------
extern "C" void kernel_launch(void* const* d_in, const int* in_sizes, int n_in,
                              void* d_out, int out_size) {
    const float* seq      = (const float*)d_in[0];
    const float* att      = (const float*)d_in[1];
    const int*   midx     = (const int*)  d_in[2];
    const float* mmask    = (const float*)d_in[3];
    const int*   hts      = (const int*)  d_in[4];
    const int*   labels   = (const int*)  d_in[5];
    const float* priors_l = (const float*)d_in[6];
    const float* priors_o = (const float*)d_in[7];
    const float* head_W   = (const float*)d_in[8];
    const float* head_b   = (const float*)d_in[9];
    const float* tail_W   = (const float*)d_in[10];
    const float* tail_b   = (const float*)d_in[11];
    const float* bil_W    = (const float*)d_in[12];
    const float* bil_b    = (const float*)d_in[13];
    float* out = (float*)d_out;

    cudaFuncSetAttribute(k_bilin_c96, cudaFuncAttributeMaxDynamicSharedMemorySize, SB_TOT);
    cudaFuncSetAttribute(k_rs_entU,   cudaFuncAttributeMaxDynamicSharedMemorySize, GEMM_SM);
    cudaFuncSetAttribute(k_rw_mma,    cudaFuncAttributeMaxDynamicSharedMemorySize, GEMM_SM);

    k_prep<<<4440, 256>>>(seq, att, midx, mmask, bil_W, head_W, tail_W);
    k_ht<<<NTOT, 256>>>(hts);
    k_rs_entU<<<168, 256, GEMM_SM>>>(head_W, tail_W);
    k_rw_mma<<<dim3(19, 12), 256, GEMM_SM>>>(hts, head_b, tail_b);
    k_bilin_c96<<<468, 256, SB_TOT>>>();
    k_logits<<<(NTOT*NL + 255)/256, 256>>>(bil_b, out);
    k_risk_all<<<RELSn, 256>>>(out, labels, priors_l, priors_o, out);
}